// round 3
// baseline (speedup 1.0000x reference)
#include <cuda_runtime.h>
#include <cstdint>

// Problem constants (Gemma4 attention): B=2, S=2048, D=2048, H=16, KV=4, HD=256
#define Bc 2
#define Sc 2048
#define Dc 2048
#define Hc 16
#define KVc 4
#define HDc 256

// Scratch (no cudaMalloc allowed): ~168 MB of __device__ globals
__device__ float g_q[(size_t)Bc * Sc * Hc * HDc];     // [B,S,H,HD]
__device__ float g_k[(size_t)Bc * Sc * KVc * HDc];    // [B,S,KV,HD]
__device__ float g_v[(size_t)Bc * Sc * KVc * HDc];    // [B,S,KV,HD]
__device__ float g_attn[(size_t)Bc * Sc * Hc * HDc];  // [B,S,H,HD]

// ===========================================================================
// TF32 tensor-core GEMM: C[M,N] = A[M,K] @ B[K,N], row-major fp32 in/out.
// CTA tile 128x128x16, 8 warps (2x4), warp tile 64x32, mma.m16n8k8.tf32.
// 4-stage cp.async pipeline. Smem: As[m][20] (banks (20m+k)%32 all-distinct),
// Bs[k][132] (banks (4k+n)%32 all-distinct) -> conflict-free fragment loads.
// ===========================================================================
#define BM 128
#define BN 128
#define BK 16
#define NSTAGE 4
#define APITCH 20
#define BPITCH 132
#define STAGEF (BM * APITCH + BK * BPITCH)   // 4672 floats per stage

__device__ __forceinline__ uint32_t f2tf(float f) {
    uint32_t r;
    asm("cvt.rna.tf32.f32 %0, %1;" : "=r"(r) : "f"(f));
    return r;
}
__device__ __forceinline__ void cpasync16(float* dst, const float* src) {
    uint32_t d = (uint32_t)__cvta_generic_to_shared(dst);
    asm volatile("cp.async.cg.shared.global [%0], [%1], 16;" :: "r"(d), "l"(src));
}

#define MMA_TF32(d, a, b) \
    asm volatile("mma.sync.aligned.m16n8k8.row.col.f32.tf32.tf32.f32 " \
                 "{%0,%1,%2,%3}, {%4,%5,%6,%7}, {%8,%9}, {%0,%1,%2,%3};" \
                 : "+f"(d[0]), "+f"(d[1]), "+f"(d[2]), "+f"(d[3]) \
                 : "r"(a[0]), "r"(a[1]), "r"(a[2]), "r"(a[3]), \
                   "r"(b[0]), "r"(b[1]))

__global__ __launch_bounds__(256) void gemm_tf32(
    const float* __restrict__ A, const float* __restrict__ B,
    float* __restrict__ C, int M, int N, int K)
{
    extern __shared__ float sm[];
    const int tid = threadIdx.x;
    const int m0 = blockIdx.y * BM, n0 = blockIdx.x * BN;
    const int warp = tid >> 5, lane = tid & 31;
    const int wm = (warp >> 2) * 64, wn = (warp & 3) * 32;

    float acc[4][4][4];
#pragma unroll
    for (int i = 0; i < 4; i++)
#pragma unroll
        for (int j = 0; j < 4; j++)
#pragma unroll
            for (int x = 0; x < 4; x++) acc[i][j][x] = 0.f;

    const int NT = K / BK;

    // --- async tile load (copies only; caller commits) ---
    auto issue = [&](int kt) {
        float* As = sm + (kt % NSTAGE) * STAGEF;
        float* Bs = As + BM * APITCH;
        const int k0 = kt * BK;
#pragma unroll
        for (int i = 0; i < 2; i++) {       // A: 128x16, 512 chunks of 16B
            int idx = tid + i * 256;
            int m = idx >> 2, c4 = (idx & 3) << 2;
            cpasync16(As + m * APITCH + c4, A + (size_t)(m0 + m) * K + k0 + c4);
        }
#pragma unroll
        for (int i = 0; i < 2; i++) {       // B: 16x128, 512 chunks of 16B
            int idx = tid + i * 256;
            int r = idx >> 5, c16 = (idx & 31) << 2;
            cpasync16(Bs + r * BPITCH + c16, B + (size_t)(k0 + r) * N + n0 + c16);
        }
    };

#pragma unroll
    for (int s = 0; s < NSTAGE - 1; s++) {
        issue(s);
        asm volatile("cp.async.commit_group;" ::: "memory");
    }

    for (int kt = 0; kt < NT; kt++) {
        asm volatile("cp.async.wait_group %0;" :: "n"(NSTAGE - 2) : "memory");
        __syncthreads();
        if (kt + NSTAGE - 1 < NT) issue(kt + NSTAGE - 1);
        asm volatile("cp.async.commit_group;" ::: "memory");   // empty group OK at tail

        const float* As = sm + (kt % NSTAGE) * STAGEF;
        const float* Bs = As + BM * APITCH;
#pragma unroll
        for (int ks = 0; ks < 2; ks++) {
            const int kb = ks * 8 + (lane & 3);
            uint32_t af[4][4], bf[4][2];
#pragma unroll
            for (int tm = 0; tm < 4; tm++) {
                int row = wm + tm * 16 + (lane >> 2);
                af[tm][0] = f2tf(As[row * APITCH + kb]);
                af[tm][1] = f2tf(As[(row + 8) * APITCH + kb]);
                af[tm][2] = f2tf(As[row * APITCH + kb + 4]);
                af[tm][3] = f2tf(As[(row + 8) * APITCH + kb + 4]);
            }
#pragma unroll
            for (int tn = 0; tn < 4; tn++) {
                int col = wn + tn * 8 + (lane >> 2);
                bf[tn][0] = f2tf(Bs[kb * BPITCH + col]);
                bf[tn][1] = f2tf(Bs[(kb + 4) * BPITCH + col]);
            }
#pragma unroll
            for (int tm = 0; tm < 4; tm++)
#pragma unroll
                for (int tn = 0; tn < 4; tn++)
                    MMA_TF32(acc[tm][tn], af[tm], bf[tn]);
        }
        __syncthreads();
    }

    // Epilogue
#pragma unroll
    for (int tm = 0; tm < 4; tm++) {
#pragma unroll
        for (int tn = 0; tn < 4; tn++) {
            int row = m0 + wm + tm * 16 + (lane >> 2);
            int col = n0 + wn + tn * 8 + 2 * (lane & 3);
            float2 lo = make_float2(acc[tm][tn][0], acc[tm][tn][1]);
            float2 hi = make_float2(acc[tm][tn][2], acc[tm][tn][3]);
            *(float2*)(C + (size_t)row * N + col) = lo;
            *(float2*)(C + (size_t)(row + 8) * N + col) = hi;
        }
    }
}

// ---------------------------------------------------------------------------
// Fused RMSNorm (eps=1e-6, weight (1+w)) + RoPE (theta=10000), in place.
// ---------------------------------------------------------------------------
__global__ __launch_bounds__(256) void rmsnorm_rope(
    float* __restrict__ buf, const float* __restrict__ w,
    const int* __restrict__ pos_ids, int nh)
{
    const int blk = blockIdx.x;          // (b*S+s)*nh + head
    const int d = threadIdx.x;           // 0..255
    const int s = (blk / nh) % Sc;
    float* x = buf + (size_t)blk * HDc;
    float v = x[d];

    float sq = v * v;
#pragma unroll
    for (int o = 16; o; o >>= 1) sq += __shfl_xor_sync(0xffffffffu, sq, o);
    __shared__ float red[8];
    __shared__ float ys[256];
    if ((d & 31) == 0) red[d >> 5] = sq;
    __syncthreads();
    float tot = red[0] + red[1] + red[2] + red[3] + red[4] + red[5] + red[6] + red[7];
    float rstd = rsqrtf(tot * (1.0f / 256.0f) + 1e-6f);
    float y = v * rstd * (1.0f + w[d]);
    ys[d] = y;
    __syncthreads();
    float partner = (d < 128) ? -ys[d + 128] : ys[d - 128];

    float p = (float)pos_ids[s];
    float inv_freq = powf(10000.0f, -(float)(d & 127) * (1.0f / 128.0f));
    float ang = p * inv_freq;
    x[d] = y * cosf(ang) + partner * sinf(ang);
}

// ---------------------------------------------------------------------------
// Flash attention, fp32, causal, GQA (kv head = h>>2), scale = 1/16.
// ---------------------------------------------------------------------------
#define FPAD 260
__global__ __launch_bounds__(256, 1) void flash_attn(
    const float* __restrict__ qb, const float* __restrict__ kb,
    const float* __restrict__ vb, float* __restrict__ ob)
{
    extern __shared__ float smf[];
    float* qs = smf;                  // 64 * FPAD
    float* ks = smf + 64 * FPAD;      // 32 * FPAD
    float* vs = smf + 96 * FPAD;      // 32 * FPAD
    const int q0 = blockIdx.x * 64;
    const int h  = blockIdx.y;
    const int b  = blockIdx.z;
    const int kvh = h >> 2;
    const int tid = threadIdx.x;
    const int w = tid >> 5, lane = tid & 31;

    for (int idx = tid; idx < 64 * 64; idx += 256) {
        int r = idx >> 6;
        int c4 = (idx & 63) << 2;
        float4 v = *(const float4*)(qb + ((size_t)((b * Sc + q0 + r) * Hc + h)) * HDc + c4);
        *(float4*)(qs + r * FPAD + c4) = v;
    }

    float acc[8][8];
#pragma unroll
    for (int r = 0; r < 8; r++)
#pragma unroll
        for (int i = 0; i < 8; i++) acc[r][i] = 0.f;
    float m[8], l[8];
#pragma unroll
    for (int r = 0; r < 8; r++) { m[r] = -3.0e38f; l[r] = 0.f; }

    const int qg_base = q0 + w * 8;
    const int ntiles = (q0 + 64) >> 5;

    for (int t = 0; t < ntiles; t++) {
        const int j0 = t << 5;
        __syncthreads();
        for (int idx = tid; idx < 32 * 64; idx += 256) {
            int r = idx >> 6;
            int c4 = (idx & 63) << 2;
            size_t g = ((size_t)((b * Sc + j0 + r) * KVc + kvh)) * HDc + c4;
            *(float4*)(ks + r * FPAD + c4) = *(const float4*)(kb + g);
            *(float4*)(vs + r * FPAD + c4) = *(const float4*)(vb + g);
        }
        __syncthreads();

        float sc[8];
#pragma unroll
        for (int r = 0; r < 8; r++) sc[r] = 0.f;
        for (int d4 = 0; d4 < 256; d4 += 4) {
            float4 k4 = *(const float4*)(ks + lane * FPAD + d4);
#pragma unroll
            for (int r = 0; r < 8; r++) {
                float4 q4 = *(const float4*)(qs + (w * 8 + r) * FPAD + d4);
                sc[r] += q4.x * k4.x + q4.y * k4.y + q4.z * k4.z + q4.w * k4.w;
            }
        }

        const int j = j0 + lane;
        float p[8];
#pragma unroll
        for (int r = 0; r < 8; r++) {
            int qg = qg_base + r;
            float s = (j <= qg) ? sc[r] * 0.0625f : -3.0e38f;
            float mx = s;
#pragma unroll
            for (int o = 16; o; o >>= 1)
                mx = fmaxf(mx, __shfl_xor_sync(0xffffffffu, mx, o));
            float mnew = fmaxf(m[r], mx);
            float pv = __expf(s - mnew);
            float alpha = __expf(m[r] - mnew);
            m[r] = mnew;
            float ps = pv;
#pragma unroll
            for (int o = 16; o; o >>= 1)
                ps += __shfl_xor_sync(0xffffffffu, ps, o);
            l[r] = l[r] * alpha + ps;
#pragma unroll
            for (int i = 0; i < 8; i++) acc[r][i] *= alpha;
            p[r] = pv;
        }

#pragma unroll 4
        for (int key = 0; key < 32; key++) {
            float vv[8];
#pragma unroll
            for (int i = 0; i < 8; i++) vv[i] = vs[key * FPAD + lane + 32 * i];
#pragma unroll
            for (int r = 0; r < 8; r++) {
                float pk = __shfl_sync(0xffffffffu, p[r], key);
#pragma unroll
                for (int i = 0; i < 8; i++) acc[r][i] += pk * vv[i];
            }
        }
    }

#pragma unroll
    for (int r = 0; r < 8; r++) {
        int qg = qg_base + r;
        float inv = 1.0f / l[r];
        float* op = ob + ((size_t)((b * Sc + qg) * Hc + h)) * HDc;
#pragma unroll
        for (int i = 0; i < 8; i++) op[lane + 32 * i] = acc[r][i] * inv;
    }
}

// ---------------------------------------------------------------------------
extern "C" void kernel_launch(void* const* d_in, const int* in_sizes, int n_in,
                              void* d_out, int out_size)
{
    const float* hidden = (const float*)d_in[0];   // [B,S,D]
    const float* Wq = (const float*)d_in[1];       // [D, H*HD]
    const float* Wk = (const float*)d_in[2];       // [D, KV*HD]
    const float* Wv = (const float*)d_in[3];       // [D, KV*HD]
    const float* Wo = (const float*)d_in[4];       // [H*HD, D]
    const float* qw = (const float*)d_in[5];       // [HD]
    const float* kw = (const float*)d_in[6];       // [HD]
    const int*  pos = (const int*)d_in[7];         // [S]
    float* out = (float*)d_out;                    // [B,S,D]

    float *qb, *kb, *vb, *ab;
    cudaGetSymbolAddress((void**)&qb, g_q);
    cudaGetSymbolAddress((void**)&kb, g_k);
    cudaGetSymbolAddress((void**)&vb, g_v);
    cudaGetSymbolAddress((void**)&ab, g_attn);

    const int M = Bc * Sc;  // 4096
    const size_t gemm_smem = (size_t)NSTAGE * STAGEF * sizeof(float);  // 74752
    cudaFuncSetAttribute(gemm_tf32, cudaFuncAttributeMaxDynamicSharedMemorySize, (int)gemm_smem);

    // QKV projections (tensor core TF32)
    gemm_tf32<<<dim3((Hc * HDc) / BN, M / BM), 256, gemm_smem>>>(hidden, Wq, qb, M, Hc * HDc, Dc);
    gemm_tf32<<<dim3((KVc * HDc) / BN, M / BM), 256, gemm_smem>>>(hidden, Wk, kb, M, KVc * HDc, Dc);
    gemm_tf32<<<dim3((KVc * HDc) / BN, M / BM), 256, gemm_smem>>>(hidden, Wv, vb, M, KVc * HDc, Dc);

    // RMSNorm + RoPE (in place) on Q and K
    rmsnorm_rope<<<M * Hc, 256>>>(qb, qw, pos, Hc);
    rmsnorm_rope<<<M * KVc, 256>>>(kb, kw, pos, KVc);

    // Flash attention (fp32 SIMT)
    size_t shmem = (size_t)128 * FPAD * sizeof(float);  // 133120 B
    cudaFuncSetAttribute(flash_attn, cudaFuncAttributeMaxDynamicSharedMemorySize, (int)shmem);
    flash_attn<<<dim3(Sc / 64, Hc, Bc), 256, shmem>>>(qb, kb, vb, ab);

    // Output projection (tensor core TF32)
    gemm_tf32<<<dim3(Dc / BN, M / BM), 256, gemm_smem>>>(ab, Wo, out, M, Dc, Hc * HDc);
}

// round 5
// speedup vs baseline: 1.9606x; 1.9606x over previous
#include <cuda_runtime.h>
#include <cuda_fp16.h>
#include <cstdint>

// Problem constants (Gemma4 attention): B=2, S=2048, D=2048, H=16, KV=4, HD=256
#define Bc 2
#define Sc 2048
#define Dc 2048
#define Hc 16
#define KVc 4
#define HDc 256

// Scratch (__device__ globals; no cudaMalloc allowed)
__device__ float  g_q[(size_t)Bc * Sc * Hc * HDc];       // [B,S,H,HD] fp32
__device__ float  g_k[(size_t)Bc * Sc * KVc * HDc];      // [B,S,KV,HD] fp32
__device__ float  g_v[(size_t)Bc * Sc * KVc * HDc];      // [B,S,KV,HD] fp32
__device__ __half g_attn_h[(size_t)Bc * Sc * Hc * HDc];  // [B,S,H*HD] fp16
__device__ __half g_hh[(size_t)Bc * Sc * Dc];            // hidden fp16 [M][K]
__device__ __half g_wqT[(size_t)(Hc * HDc) * Dc];        // [4096][2048] fp16
__device__ __half g_wkT[(size_t)(KVc * HDc) * Dc];       // [1024][2048]
__device__ __half g_wvT[(size_t)(KVc * HDc) * Dc];       // [1024][2048]
__device__ __half g_woT[(size_t)Dc * (Hc * HDc)];        // [2048][4096]

// ===========================================================================
// fp16 mma.sync GEMM: C[M,N](fp32) = A[M,K](fp16) @ Bt[N,K](fp16)^T
// CTA tile 128x128, K-stage 64, 8 warps (2x4), warp tile 64x32.
// mma.m16n8k16.row.col.f32.f16.f16.f32. 2-stage cp.async double buffer.
// Smem pitch 72 halves: fragment LDS.32 banks = (4r+c)%32, all distinct.
// ===========================================================================
#define BM 128
#define BN 128
#define BKH 64
#define PITCH 72
#define STAGE_HALF (2 * 128 * PITCH)            // A+B per stage, halves
#define GEMM_SMEM (2 * STAGE_HALF * 2)          // bytes = 73728

__device__ __forceinline__ void cpasync16(const void* smem_dst, const void* gsrc) {
    uint32_t d = (uint32_t)__cvta_generic_to_shared(smem_dst);
    asm volatile("cp.async.cg.shared.global [%0], [%1], 16;" :: "r"(d), "l"(gsrc));
}
#define CP_COMMIT() asm volatile("cp.async.commit_group;" ::: "memory")
#define CP_WAIT1()  asm volatile("cp.async.wait_group 1;" ::: "memory")

#define MMA_F16(d, a, b) \
    asm volatile("mma.sync.aligned.m16n8k16.row.col.f32.f16.f16.f32 " \
                 "{%0,%1,%2,%3}, {%4,%5,%6,%7}, {%8,%9}, {%0,%1,%2,%3};" \
                 : "+f"(d[0]), "+f"(d[1]), "+f"(d[2]), "+f"(d[3]) \
                 : "r"(a[0]), "r"(a[1]), "r"(a[2]), "r"(a[3]), \
                   "r"(b[0]), "r"(b[1]))

__global__ __launch_bounds__(256, 2) void gemm_f16(
    const __half* __restrict__ A, const __half* __restrict__ Bt,
    float* __restrict__ C, int M, int N, int K)
{
    extern __shared__ __half smh[];
    const int tid = threadIdx.x;
    const int warp = tid >> 5, lane = tid & 31;
    const int wm = (warp >> 2) * 64, wn = (warp & 3) * 32;
    const int m0 = blockIdx.y * BM, n0 = blockIdx.x * BN;
    const int NT = K / BKH;

    float acc[4][4][4];
#pragma unroll
    for (int i = 0; i < 4; i++)
#pragma unroll
        for (int j = 0; j < 4; j++)
#pragma unroll
            for (int x = 0; x < 4; x++) acc[i][j][x] = 0.f;

    auto issue = [&](int kt) {
        __half* st = smh + (kt & 1) * STAGE_HALF;
        __half* As = st;
        __half* Bs = st + 128 * PITCH;
        const __half* Ag = A + (size_t)m0 * K + kt * BKH;
        const __half* Bg = Bt + (size_t)n0 * K + kt * BKH;
#pragma unroll
        for (int i = 0; i < 4; i++) {
            int idx = tid + i * 256;          // 0..1023
            int r = idx >> 3, ch = idx & 7;   // row, 16B chunk (8 halves)
            cpasync16(As + r * PITCH + ch * 8, Ag + (size_t)r * K + ch * 8);
        }
#pragma unroll
        for (int i = 0; i < 4; i++) {
            int idx = tid + i * 256;
            int r = idx >> 3, ch = idx & 7;
            cpasync16(Bs + r * PITCH + ch * 8, Bg + (size_t)r * K + ch * 8);
        }
    };

    issue(0);
    CP_COMMIT();

    for (int kt = 0; kt < NT; kt++) {
        if (kt + 1 < NT) issue(kt + 1);
        CP_COMMIT();
        CP_WAIT1();
        __syncthreads();

        const __half* As = smh + (kt & 1) * STAGE_HALF;
        const __half* Bs = As + 128 * PITCH;
#pragma unroll
        for (int kc = 0; kc < 4; kc++) {
            const int c0 = kc * 16 + 2 * (lane & 3);
            const int rq = lane >> 2;
            uint32_t a[4][4], b[4][2];
#pragma unroll
            for (int tm = 0; tm < 4; tm++) {
                int r = wm + tm * 16 + rq;
                a[tm][0] = *(const uint32_t*)(As + r * PITCH + c0);
                a[tm][1] = *(const uint32_t*)(As + (r + 8) * PITCH + c0);
                a[tm][2] = *(const uint32_t*)(As + r * PITCH + c0 + 8);
                a[tm][3] = *(const uint32_t*)(As + (r + 8) * PITCH + c0 + 8);
            }
#pragma unroll
            for (int tn = 0; tn < 4; tn++) {
                int n = wn + tn * 8 + rq;
                b[tn][0] = *(const uint32_t*)(Bs + n * PITCH + c0);
                b[tn][1] = *(const uint32_t*)(Bs + n * PITCH + c0 + 8);
            }
#pragma unroll
            for (int tm = 0; tm < 4; tm++)
#pragma unroll
                for (int tn = 0; tn < 4; tn++)
                    MMA_F16(acc[tm][tn], a[tm], b[tn]);
        }
        __syncthreads();
    }

    // Epilogue: direct fp32 stores (proven mapping)
#pragma unroll
    for (int tm = 0; tm < 4; tm++) {
#pragma unroll
        for (int tn = 0; tn < 4; tn++) {
            int row = m0 + wm + tm * 16 + (lane >> 2);
            int col = n0 + wn + tn * 8 + 2 * (lane & 3);
            *(float2*)(C + (size_t)row * N + col) =
                make_float2(acc[tm][tn][0], acc[tm][tn][1]);
            *(float2*)(C + (size_t)(row + 8) * N + col) =
                make_float2(acc[tm][tn][2], acc[tm][tn][3]);
        }
    }
}

// ---------------------------------------------------------------------------
// Prep: fp32 -> fp16 copy (activations)
// ---------------------------------------------------------------------------
__global__ __launch_bounds__(256) void to_half(const float4* __restrict__ src,
                                               __half* __restrict__ dst, int n4)
{
    int i = blockIdx.x * 256 + threadIdx.x;
    if (i < n4) {
        float4 v = src[i];
        __half2* d = (__half2*)(dst + (size_t)i * 4);
        d[0] = __floats2half2_rn(v.x, v.y);
        d[1] = __floats2half2_rn(v.z, v.w);
    }
}

// ---------------------------------------------------------------------------
// Prep: transpose fp32 [R][C] -> fp16 [C][R]
// ---------------------------------------------------------------------------
__global__ __launch_bounds__(256) void transpose_half(
    const float* __restrict__ src, __half* __restrict__ dst, int R, int C)
{
    __shared__ float t[32][33];
    const int bx = blockIdx.x * 32;   // C offset
    const int by = blockIdx.y * 32;   // R offset
    const int x = threadIdx.x & 31;
    const int y0 = (threadIdx.x >> 5) * 4;
#pragma unroll
    for (int j = 0; j < 4; j++)
        t[y0 + j][x] = src[(size_t)(by + y0 + j) * C + bx + x];
    __syncthreads();
#pragma unroll
    for (int j = 0; j < 4; j++)
        dst[(size_t)(bx + y0 + j) * R + by + x] = __float2half_rn(t[x][y0 + j]);
}

// ---------------------------------------------------------------------------
// Fused RMSNorm (eps=1e-6, weight (1+w)) + RoPE (theta=10000), in place.
// ---------------------------------------------------------------------------
__global__ __launch_bounds__(256) void rmsnorm_rope(
    float* __restrict__ buf, const float* __restrict__ w,
    const int* __restrict__ pos_ids, int nh)
{
    const int blk = blockIdx.x;
    const int d = threadIdx.x;
    const int s = (blk / nh) % Sc;
    float* x = buf + (size_t)blk * HDc;
    float v = x[d];

    float sq = v * v;
#pragma unroll
    for (int o = 16; o; o >>= 1) sq += __shfl_xor_sync(0xffffffffu, sq, o);
    __shared__ float red[8];
    __shared__ float ys[256];
    if ((d & 31) == 0) red[d >> 5] = sq;
    __syncthreads();
    float tot = red[0] + red[1] + red[2] + red[3] + red[4] + red[5] + red[6] + red[7];
    float rstd = rsqrtf(tot * (1.0f / 256.0f) + 1e-6f);
    float y = v * rstd * (1.0f + w[d]);
    ys[d] = y;
    __syncthreads();
    float partner = (d < 128) ? -ys[d + 128] : ys[d - 128];

    float p = (float)pos_ids[s];
    float inv_freq = powf(10000.0f, -(float)(d & 127) * (1.0f / 128.0f));
    float ang = p * inv_freq;
    x[d] = y * cosf(ang) + partner * sinf(ang);
}

// ---------------------------------------------------------------------------
// Flash attention, fp32, causal, GQA (kv head = h>>2), scale = 1/16.
// Epilogue writes fp16 (feeds O-projection fp16 GEMM).
// ---------------------------------------------------------------------------
#define FPAD 260
__global__ __launch_bounds__(256, 1) void flash_attn(
    const float* __restrict__ qb, const float* __restrict__ kb,
    const float* __restrict__ vb, __half* __restrict__ ob)
{
    extern __shared__ float smf[];
    float* qs = smf;                  // 64 * FPAD
    float* ks = smf + 64 * FPAD;      // 32 * FPAD
    float* vs = smf + 96 * FPAD;      // 32 * FPAD
    const int q0 = blockIdx.x * 64;
    const int h  = blockIdx.y;
    const int b  = blockIdx.z;
    const int kvh = h >> 2;
    const int tid = threadIdx.x;
    const int w = tid >> 5, lane = tid & 31;

    for (int idx = tid; idx < 64 * 64; idx += 256) {
        int r = idx >> 6;
        int c4 = (idx & 63) << 2;
        float4 v = *(const float4*)(qb + ((size_t)((b * Sc + q0 + r) * Hc + h)) * HDc + c4);
        *(float4*)(qs + r * FPAD + c4) = v;
    }

    float acc[8][8];
#pragma unroll
    for (int r = 0; r < 8; r++)
#pragma unroll
        for (int i = 0; i < 8; i++) acc[r][i] = 0.f;
    float m[8], l[8];
#pragma unroll
    for (int r = 0; r < 8; r++) { m[r] = -3.0e38f; l[r] = 0.f; }

    const int qg_base = q0 + w * 8;
    const int ntiles = (q0 + 64) >> 5;

    for (int t = 0; t < ntiles; t++) {
        const int j0 = t << 5;
        __syncthreads();
        for (int idx = tid; idx < 32 * 64; idx += 256) {
            int r = idx >> 6;
            int c4 = (idx & 63) << 2;
            size_t g = ((size_t)((b * Sc + j0 + r) * KVc + kvh)) * HDc + c4;
            *(float4*)(ks + r * FPAD + c4) = *(const float4*)(kb + g);
            *(float4*)(vs + r * FPAD + c4) = *(const float4*)(vb + g);
        }
        __syncthreads();

        float sc[8];
#pragma unroll
        for (int r = 0; r < 8; r++) sc[r] = 0.f;
        for (int d4 = 0; d4 < 256; d4 += 4) {
            float4 k4 = *(const float4*)(ks + lane * FPAD + d4);
#pragma unroll
            for (int r = 0; r < 8; r++) {
                float4 q4 = *(const float4*)(qs + (w * 8 + r) * FPAD + d4);
                sc[r] += q4.x * k4.x + q4.y * k4.y + q4.z * k4.z + q4.w * k4.w;
            }
        }

        const int j = j0 + lane;
        float p[8];
#pragma unroll
        for (int r = 0; r < 8; r++) {
            int qg = qg_base + r;
            float s = (j <= qg) ? sc[r] * 0.0625f : -3.0e38f;
            float mx = s;
#pragma unroll
            for (int o = 16; o; o >>= 1)
                mx = fmaxf(mx, __shfl_xor_sync(0xffffffffu, mx, o));
            float mnew = fmaxf(m[r], mx);
            float pv = __expf(s - mnew);
            float alpha = __expf(m[r] - mnew);
            m[r] = mnew;
            float ps = pv;
#pragma unroll
            for (int o = 16; o; o >>= 1)
                ps += __shfl_xor_sync(0xffffffffu, ps, o);
            l[r] = l[r] * alpha + ps;
#pragma unroll
            for (int i = 0; i < 8; i++) acc[r][i] *= alpha;
            p[r] = pv;
        }

#pragma unroll 4
        for (int key = 0; key < 32; key++) {
            float vv[8];
#pragma unroll
            for (int i = 0; i < 8; i++) vv[i] = vs[key * FPAD + lane + 32 * i];
#pragma unroll
            for (int r = 0; r < 8; r++) {
                float pk = __shfl_sync(0xffffffffu, p[r], key);
#pragma unroll
                for (int i = 0; i < 8; i++) acc[r][i] += pk * vv[i];
            }
        }
    }

#pragma unroll
    for (int r = 0; r < 8; r++) {
        int qg = qg_base + r;
        float inv = 1.0f / l[r];
        __half* op = ob + ((size_t)((b * Sc + qg) * Hc + h)) * HDc;
#pragma unroll
        for (int i = 0; i < 8; i++)
            op[lane + 32 * i] = __float2half_rn(acc[r][i] * inv);
    }
}

// ---------------------------------------------------------------------------
extern "C" void kernel_launch(void* const* d_in, const int* in_sizes, int n_in,
                              void* d_out, int out_size)
{
    const float* hidden = (const float*)d_in[0];   // [B,S,D]
    const float* Wq = (const float*)d_in[1];       // [D, H*HD]
    const float* Wk = (const float*)d_in[2];       // [D, KV*HD]
    const float* Wv = (const float*)d_in[3];       // [D, KV*HD]
    const float* Wo = (const float*)d_in[4];       // [H*HD, D]
    const float* qw = (const float*)d_in[5];       // [HD]
    const float* kw = (const float*)d_in[6];       // [HD]
    const int*  pos = (const int*)d_in[7];         // [S]
    float* out = (float*)d_out;                    // [B,S,D]

    float *qb, *kb, *vb;
    __half *ah, *hh, *wqT, *wkT, *wvT, *woT;
    cudaGetSymbolAddress((void**)&qb, g_q);
    cudaGetSymbolAddress((void**)&kb, g_k);
    cudaGetSymbolAddress((void**)&vb, g_v);
    cudaGetSymbolAddress((void**)&ah, g_attn_h);
    cudaGetSymbolAddress((void**)&hh, g_hh);
    cudaGetSymbolAddress((void**)&wqT, g_wqT);
    cudaGetSymbolAddress((void**)&wkT, g_wkT);
    cudaGetSymbolAddress((void**)&wvT, g_wvT);
    cudaGetSymbolAddress((void**)&woT, g_woT);

    const int M = Bc * Sc;           // 4096
    const int NQ = Hc * HDc;         // 4096
    const int NKV = KVc * HDc;       // 1024

    cudaFuncSetAttribute(gemm_f16, cudaFuncAttributeMaxDynamicSharedMemorySize, GEMM_SMEM);

    // Prep: hidden -> fp16; weights -> transposed fp16 [N][K]
    {
        int n4 = M * Dc / 4;
        to_half<<<(n4 + 255) / 256, 256>>>((const float4*)hidden, hh, n4);
    }
    transpose_half<<<dim3(NQ / 32, Dc / 32), 256>>>(Wq, wqT, Dc, NQ);
    transpose_half<<<dim3(NKV / 32, Dc / 32), 256>>>(Wk, wkT, Dc, NKV);
    transpose_half<<<dim3(NKV / 32, Dc / 32), 256>>>(Wv, wvT, Dc, NKV);
    transpose_half<<<dim3(Dc / 32, NQ / 32), 256>>>(Wo, woT, NQ, Dc);

    // QKV projections (fp16 tensor core, fp32 accumulate)
    gemm_f16<<<dim3(NQ / BN, M / BM), 256, GEMM_SMEM>>>(hh, wqT, qb, M, NQ, Dc);
    gemm_f16<<<dim3(NKV / BN, M / BM), 256, GEMM_SMEM>>>(hh, wkT, kb, M, NKV, Dc);
    gemm_f16<<<dim3(NKV / BN, M / BM), 256, GEMM_SMEM>>>(hh, wvT, vb, M, NKV, Dc);

    // RMSNorm + RoPE (in place) on Q and K
    rmsnorm_rope<<<M * Hc, 256>>>(qb, qw, pos, Hc);
    rmsnorm_rope<<<M * KVc, 256>>>(kb, kw, pos, KVc);

    // Flash attention (fp32 SIMT, fp16 output)
    size_t shmem = (size_t)128 * FPAD * sizeof(float);  // 133120 B
    cudaFuncSetAttribute(flash_attn, cudaFuncAttributeMaxDynamicSharedMemorySize, (int)shmem);
    flash_attn<<<dim3(Sc / 64, Hc, Bc), 256, shmem>>>(qb, kb, vb, ah);

    // Output projection (fp16 tensor core)
    gemm_f16<<<dim3(Dc / BN, M / BM), 256, GEMM_SMEM>>>(ah, woT, out, M, Dc, NQ);
}

// round 6
// speedup vs baseline: 6.1452x; 3.1343x over previous
#include <cuda_runtime.h>
#include <cuda_fp16.h>
#include <cstdint>

// Problem constants (Gemma4 attention): B=2, S=2048, D=2048, H=16, KV=4, HD=256
#define Bc 2
#define Sc 2048
#define Dc 2048
#define Hc 16
#define KVc 4
#define HDc 256

// Scratch (__device__ globals; no cudaMalloc allowed)
__device__ float  g_q[(size_t)Bc * Sc * Hc * HDc];       // QKV gemm out fp32
__device__ float  g_k[(size_t)Bc * Sc * KVc * HDc];
__device__ float  g_v[(size_t)Bc * Sc * KVc * HDc];
__device__ __half g_qh[(size_t)Bc * Hc * Sc * HDc];      // [b][h][s][d] fp16
__device__ __half g_kh[(size_t)Bc * KVc * Sc * HDc];     // [b][kv][s][d]
__device__ __half g_vt[(size_t)Bc * KVc * HDc * Sc];     // [b][kv][d][s]
__device__ __half g_attn_h[(size_t)Bc * Sc * Hc * HDc];  // [b,s][h*HD] fp16
__device__ __half g_hh[(size_t)Bc * Sc * Dc];            // hidden fp16
__device__ __half g_wqT[(size_t)(Hc * HDc) * Dc];
__device__ __half g_wkT[(size_t)(KVc * HDc) * Dc];
__device__ __half g_wvT[(size_t)(KVc * HDc) * Dc];
__device__ __half g_woT[(size_t)Dc * (Hc * HDc)];

// ===========================================================================
// Common PTX helpers
// ===========================================================================
__device__ __forceinline__ void cpasync16(const void* smem_dst, const void* gsrc) {
    uint32_t d = (uint32_t)__cvta_generic_to_shared(smem_dst);
    asm volatile("cp.async.cg.shared.global [%0], [%1], 16;" :: "r"(d), "l"(gsrc));
}
#define CP_COMMIT() asm volatile("cp.async.commit_group;" ::: "memory")
#define CP_WAIT0()  asm volatile("cp.async.wait_group 0;" ::: "memory")
#define CP_WAIT1()  asm volatile("cp.async.wait_group 1;" ::: "memory")

#define MMA_F16(d, a, b) \
    asm volatile("mma.sync.aligned.m16n8k16.row.col.f32.f16.f16.f32 " \
                 "{%0,%1,%2,%3}, {%4,%5,%6,%7}, {%8,%9}, {%0,%1,%2,%3};" \
                 : "+f"(d[0]), "+f"(d[1]), "+f"(d[2]), "+f"(d[3]) \
                 : "r"(a[0]), "r"(a[1]), "r"(a[2]), "r"(a[3]), \
                   "r"(b[0]), "r"(b[1]))

// ===========================================================================
// fp16 mma.sync GEMM (unchanged from round 5; passing at ~170 TF/s)
// ===========================================================================
#define BM 128
#define BN 128
#define BKH 64
#define PITCH 72
#define STAGE_HALF (2 * 128 * PITCH)
#define GEMM_SMEM (2 * STAGE_HALF * 2)

__global__ __launch_bounds__(256, 2) void gemm_f16(
    const __half* __restrict__ A, const __half* __restrict__ Bt,
    float* __restrict__ C, int M, int N, int K)
{
    extern __shared__ __half smh[];
    const int tid = threadIdx.x;
    const int warp = tid >> 5, lane = tid & 31;
    const int wm = (warp >> 2) * 64, wn = (warp & 3) * 32;
    const int m0 = blockIdx.y * BM, n0 = blockIdx.x * BN;
    const int NT = K / BKH;

    float acc[4][4][4];
#pragma unroll
    for (int i = 0; i < 4; i++)
#pragma unroll
        for (int j = 0; j < 4; j++)
#pragma unroll
            for (int x = 0; x < 4; x++) acc[i][j][x] = 0.f;

    auto issue = [&](int kt) {
        __half* st = smh + (kt & 1) * STAGE_HALF;
        __half* As = st;
        __half* Bs = st + 128 * PITCH;
        const __half* Ag = A + (size_t)m0 * K + kt * BKH;
        const __half* Bg = Bt + (size_t)n0 * K + kt * BKH;
#pragma unroll
        for (int i = 0; i < 4; i++) {
            int idx = tid + i * 256;
            int r = idx >> 3, ch = idx & 7;
            cpasync16(As + r * PITCH + ch * 8, Ag + (size_t)r * K + ch * 8);
        }
#pragma unroll
        for (int i = 0; i < 4; i++) {
            int idx = tid + i * 256;
            int r = idx >> 3, ch = idx & 7;
            cpasync16(Bs + r * PITCH + ch * 8, Bg + (size_t)r * K + ch * 8);
        }
    };

    issue(0);
    CP_COMMIT();

    for (int kt = 0; kt < NT; kt++) {
        if (kt + 1 < NT) issue(kt + 1);
        CP_COMMIT();
        CP_WAIT1();
        __syncthreads();

        const __half* As = smh + (kt & 1) * STAGE_HALF;
        const __half* Bs = As + 128 * PITCH;
#pragma unroll
        for (int kc = 0; kc < 4; kc++) {
            const int c0 = kc * 16 + 2 * (lane & 3);
            const int rq = lane >> 2;
            uint32_t a[4][4], b[4][2];
#pragma unroll
            for (int tm = 0; tm < 4; tm++) {
                int r = wm + tm * 16 + rq;
                a[tm][0] = *(const uint32_t*)(As + r * PITCH + c0);
                a[tm][1] = *(const uint32_t*)(As + (r + 8) * PITCH + c0);
                a[tm][2] = *(const uint32_t*)(As + r * PITCH + c0 + 8);
                a[tm][3] = *(const uint32_t*)(As + (r + 8) * PITCH + c0 + 8);
            }
#pragma unroll
            for (int tn = 0; tn < 4; tn++) {
                int n = wn + tn * 8 + rq;
                b[tn][0] = *(const uint32_t*)(Bs + n * PITCH + c0);
                b[tn][1] = *(const uint32_t*)(Bs + n * PITCH + c0 + 8);
            }
#pragma unroll
            for (int tm = 0; tm < 4; tm++)
#pragma unroll
                for (int tn = 0; tn < 4; tn++)
                    MMA_F16(acc[tm][tn], a[tm], b[tn]);
        }
        __syncthreads();
    }

#pragma unroll
    for (int tm = 0; tm < 4; tm++) {
#pragma unroll
        for (int tn = 0; tn < 4; tn++) {
            int row = m0 + wm + tm * 16 + (lane >> 2);
            int col = n0 + wn + tn * 8 + 2 * (lane & 3);
            *(float2*)(C + (size_t)row * N + col) =
                make_float2(acc[tm][tn][0], acc[tm][tn][1]);
            *(float2*)(C + (size_t)(row + 8) * N + col) =
                make_float2(acc[tm][tn][2], acc[tm][tn][3]);
        }
    }
}

// ---------------------------------------------------------------------------
// Prep kernels
// ---------------------------------------------------------------------------
__global__ __launch_bounds__(256) void to_half(const float4* __restrict__ src,
                                               __half* __restrict__ dst, int n4)
{
    int i = blockIdx.x * 256 + threadIdx.x;
    if (i < n4) {
        float4 v = src[i];
        __half2* d = (__half2*)(dst + (size_t)i * 4);
        d[0] = __floats2half2_rn(v.x, v.y);
        d[1] = __floats2half2_rn(v.z, v.w);
    }
}

__global__ __launch_bounds__(256) void transpose_half(
    const float* __restrict__ src, __half* __restrict__ dst, int R, int C)
{
    __shared__ float t[32][33];
    const int bx = blockIdx.x * 32;
    const int by = blockIdx.y * 32;
    const int x = threadIdx.x & 31;
    const int y0 = (threadIdx.x >> 5) * 4;
#pragma unroll
    for (int j = 0; j < 4; j++)
        t[y0 + j][x] = src[(size_t)(by + y0 + j) * C + bx + x];
    __syncthreads();
#pragma unroll
    for (int j = 0; j < 4; j++)
        dst[(size_t)(bx + y0 + j) * R + by + x] = __float2half_rn(t[x][y0 + j]);
}

// V fp32 [b,s][kv*256+d] -> Vt fp16 [b][kv][d][s]
__global__ __launch_bounds__(256) void transpose_vt(
    const float* __restrict__ v, __half* __restrict__ vt)
{
    __shared__ float t[32][33];
    const int bkv = blockIdx.z;
    const int b = bkv >> 2, kv = bkv & 3;
    const int s0 = blockIdx.y * 32;
    const int d0 = blockIdx.x * 32;
    const int x = threadIdx.x & 31;
    const int y0 = (threadIdx.x >> 5) * 4;
#pragma unroll
    for (int j = 0; j < 4; j++)
        t[y0 + j][x] = v[(size_t)(b * Sc + s0 + y0 + j) * (KVc * HDc) + kv * HDc + d0 + x];
    __syncthreads();
#pragma unroll
    for (int j = 0; j < 4; j++)
        vt[(size_t)(bkv * HDc + d0 + y0 + j) * Sc + s0 + x] = __float2half_rn(t[x][y0 + j]);
}

// ---------------------------------------------------------------------------
// RMSNorm + RoPE, fp32 in -> fp16 out in head-major layout [b][head][s][d]
// ---------------------------------------------------------------------------
__global__ __launch_bounds__(256) void rmsnorm_rope_h(
    const float* __restrict__ in, __half* __restrict__ outh,
    const float* __restrict__ w, const int* __restrict__ pos_ids, int nh)
{
    const int blk = blockIdx.x;           // (b*S+s)*nh + head
    const int d = threadIdx.x;
    const int head = blk % nh;
    const int bs = blk / nh;
    const int s = bs % Sc, b = bs / Sc;
    const float* x = in + (size_t)blk * HDc;
    float v = x[d];

    float sq = v * v;
#pragma unroll
    for (int o = 16; o; o >>= 1) sq += __shfl_xor_sync(0xffffffffu, sq, o);
    __shared__ float red[8];
    __shared__ float ys[256];
    if ((d & 31) == 0) red[d >> 5] = sq;
    __syncthreads();
    float tot = red[0] + red[1] + red[2] + red[3] + red[4] + red[5] + red[6] + red[7];
    float rstd = rsqrtf(tot * (1.0f / 256.0f) + 1e-6f);
    float y = v * rstd * (1.0f + w[d]);
    ys[d] = y;
    __syncthreads();
    float partner = (d < 128) ? -ys[d + 128] : ys[d - 128];

    float p = (float)pos_ids[s];
    float inv_freq = powf(10000.0f, -(float)(d & 127) * (1.0f / 128.0f));
    float ang = p * inv_freq;
    outh[((size_t)(b * nh + head) * Sc + s) * HDc + d] =
        __float2half_rn(y * cosf(ang) + partner * sinf(ang));
}

// ===========================================================================
// Tensor-core flash attention.
// CTA: 64 q rows, 256 threads = 8 warps = 4 row-groups (rg, 16 q each)
//      x 2 d-halves (dh, 128 each). Key tiles of 64, cp.async double buffer.
// S split by d-half, summed via smem; dh0 warps do softmax; P via smem fp16.
// ===========================================================================
#define QP 264   // halves pitch, Q/K tiles
#define VP 72    // halves pitch, Vt tile
#define SP 65    // floats pitch, S exchange
#define PP 72    // halves pitch, P tile
#define OFF_KS (64 * QP)                       // halves
#define OFF_VS (OFF_KS + 2 * 64 * QP)          // halves
#define OFF_SS ((OFF_VS + 2 * 256 * VP) * 2)   // bytes from here
#define OFF_PS (OFF_SS + 4 * 16 * SP * 4)
#define OFF_AS (OFF_PS + 4 * 16 * PP * 2)
#define OFF_LS (OFF_AS + 64 * 4)
#define FLASH_SMEM (OFF_LS + 64 * 4)           // 201472 bytes

__global__ __launch_bounds__(256, 1) void flash_attn_tc(
    const __half* __restrict__ qh, const __half* __restrict__ kh,
    const __half* __restrict__ vt, __half* __restrict__ ob)
{
    extern __shared__ char smc[];
    __half* Qs  = (__half*)smc;
    __half* Ks0 = Qs + OFF_KS;
    __half* Vs0 = Qs + OFF_VS;
    float*  Ssm = (float*)(smc + OFF_SS);
    __half* Psm = (__half*)(smc + OFF_PS);
    float*  Asm = (float*)(smc + OFF_AS);
    float*  Lsm = (float*)(smc + OFF_LS);

    const int qt = gridDim.x - 1 - blockIdx.x;   // heavy tiles first
    const int q0 = qt * 64;
    const int h = blockIdx.y, b = blockIdx.z;
    const int kvh = h >> 2;
    const int tid = threadIdx.x;
    const int w = tid >> 5, lane = tid & 31;
    const int rg = w & 3, dh = w >> 2;
    const int lr = lane >> 2, lc = lane & 3;

    const __half* Qg = qh + ((size_t)(b * Hc + h) * Sc + q0) * HDc;
    const __half* Kg = kh + ((size_t)(b * KVc + kvh) * Sc) * HDc;
    const __half* Vg = vt + ((size_t)(b * KVc + kvh) * HDc) * Sc;

    auto issue_kv = [&](int t, int buf) {
        const int j0 = t * 64;
        __half* Kd = Ks0 + buf * 64 * QP;
        __half* Vd = Vs0 + buf * 256 * VP;
#pragma unroll
        for (int i = 0; i < 8; i++) {          // K: 64 rows x 32 chunks
            int idx = tid + i * 256;
            int r = idx >> 5, ch = idx & 31;
            cpasync16(Kd + r * QP + ch * 8, Kg + (size_t)(j0 + r) * HDc + ch * 8);
        }
#pragma unroll
        for (int i = 0; i < 8; i++) {          // Vt: 256 rows x 8 chunks
            int idx = tid + i * 256;
            int r = idx >> 3, ch = idx & 7;
            cpasync16(Vd + r * VP + ch * 8, Vg + (size_t)r * Sc + j0 + ch * 8);
        }
    };

    // Q tile + first K/V tile
#pragma unroll
    for (int i = 0; i < 8; i++) {
        int idx = tid + i * 256;
        int r = idx >> 5, ch = idx & 31;
        cpasync16(Qs + r * QP + ch * 8, Qg + (size_t)r * HDc + ch * 8);
    }
    issue_kv(0, 0);
    CP_COMMIT();

    float oacc[16][4];
#pragma unroll
    for (int i = 0; i < 16; i++)
#pragma unroll
        for (int j = 0; j < 4; j++) oacc[i][j] = 0.f;
    float m0v = -1e30f, m1v = -1e30f, l0 = 0.f, l1 = 0.f;
    float alpha0 = 1.f, alpha1 = 1.f;

    const int qg0 = q0 + rg * 16 + lr;
    const int qg1 = qg0 + 8;
    const int ntiles = q0 / 64 + 1;

    for (int t = 0; t < ntiles; t++) {
        CP_WAIT0();
        __syncthreads();
        if (t + 1 < ntiles) { issue_kv(t + 1, (t + 1) & 1); CP_COMMIT(); }

        const __half* Kb = Ks0 + (t & 1) * 64 * QP;
        const __half* Vb = Vs0 + (t & 1) * 256 * VP;
        const int j0 = t * 64;

        // ---- S (own d-half) ----
        float sacc[8][4];
#pragma unroll
        for (int i = 0; i < 8; i++)
#pragma unroll
            for (int j = 0; j < 4; j++) sacc[i][j] = 0.f;
#pragma unroll
        for (int kc = 0; kc < 8; kc++) {
            const int c0 = dh * 128 + kc * 16 + 2 * lc;
            const int r = rg * 16 + lr;
            uint32_t a[4];
            a[0] = *(const uint32_t*)(Qs + r * QP + c0);
            a[1] = *(const uint32_t*)(Qs + (r + 8) * QP + c0);
            a[2] = *(const uint32_t*)(Qs + r * QP + c0 + 8);
            a[3] = *(const uint32_t*)(Qs + (r + 8) * QP + c0 + 8);
#pragma unroll
            for (int nf = 0; nf < 8; nf++) {
                int n = nf * 8 + lr;
                uint32_t bb[2];
                bb[0] = *(const uint32_t*)(Kb + n * QP + c0);
                bb[1] = *(const uint32_t*)(Kb + n * QP + c0 + 8);
                MMA_F16(sacc[nf], a, bb);
            }
        }

        if (dh == 1) {   // publish my half
            float* S = Ssm + rg * 16 * SP;
#pragma unroll
            for (int nf = 0; nf < 8; nf++) {
                int col = 8 * nf + 2 * lc;
                S[lr * SP + col]           = sacc[nf][0];
                S[lr * SP + col + 1]       = sacc[nf][1];
                S[(lr + 8) * SP + col]     = sacc[nf][2];
                S[(lr + 8) * SP + col + 1] = sacc[nf][3];
            }
        }
        __syncthreads();

        if (dh == 0) {   // full S, softmax, publish P + alpha
            const float* S = Ssm + rg * 16 * SP;
            const bool lastt = (t == ntiles - 1);
#pragma unroll
            for (int nf = 0; nf < 8; nf++) {
                int col = 8 * nf + 2 * lc;
                float s0 = (sacc[nf][0] + S[lr * SP + col]) * 0.0625f;
                float s1 = (sacc[nf][1] + S[lr * SP + col + 1]) * 0.0625f;
                float s2 = (sacc[nf][2] + S[(lr + 8) * SP + col]) * 0.0625f;
                float s3 = (sacc[nf][3] + S[(lr + 8) * SP + col + 1]) * 0.0625f;
                if (lastt) {
                    int j = j0 + col;
                    if (j > qg0)     s0 = -1e30f;
                    if (j + 1 > qg0) s1 = -1e30f;
                    if (j > qg1)     s2 = -1e30f;
                    if (j + 1 > qg1) s3 = -1e30f;
                }
                sacc[nf][0] = s0; sacc[nf][1] = s1; sacc[nf][2] = s2; sacc[nf][3] = s3;
            }
            float mx0 = -1e30f, mx1 = -1e30f;
#pragma unroll
            for (int nf = 0; nf < 8; nf++) {
                mx0 = fmaxf(mx0, fmaxf(sacc[nf][0], sacc[nf][1]));
                mx1 = fmaxf(mx1, fmaxf(sacc[nf][2], sacc[nf][3]));
            }
            mx0 = fmaxf(mx0, __shfl_xor_sync(0xffffffffu, mx0, 1));
            mx0 = fmaxf(mx0, __shfl_xor_sync(0xffffffffu, mx0, 2));
            mx1 = fmaxf(mx1, __shfl_xor_sync(0xffffffffu, mx1, 1));
            mx1 = fmaxf(mx1, __shfl_xor_sync(0xffffffffu, mx1, 2));
            float mn0 = fmaxf(m0v, mx0), mn1 = fmaxf(m1v, mx1);
            alpha0 = __expf(m0v - mn0);
            alpha1 = __expf(m1v - mn1);
            m0v = mn0; m1v = mn1;

            __half* P = Psm + rg * 16 * PP;
            float ps0 = 0.f, ps1 = 0.f;
#pragma unroll
            for (int nf = 0; nf < 8; nf++) {
                int col = 8 * nf + 2 * lc;
                float p0 = __expf(sacc[nf][0] - mn0);
                float p1 = __expf(sacc[nf][1] - mn0);
                float p2 = __expf(sacc[nf][2] - mn1);
                float p3 = __expf(sacc[nf][3] - mn1);
                ps0 += p0 + p1; ps1 += p2 + p3;
                *(__half2*)(P + lr * PP + col)       = __floats2half2_rn(p0, p1);
                *(__half2*)(P + (lr + 8) * PP + col) = __floats2half2_rn(p2, p3);
            }
            ps0 += __shfl_xor_sync(0xffffffffu, ps0, 1);
            ps0 += __shfl_xor_sync(0xffffffffu, ps0, 2);
            ps1 += __shfl_xor_sync(0xffffffffu, ps1, 1);
            ps1 += __shfl_xor_sync(0xffffffffu, ps1, 2);
            l0 = l0 * alpha0 + ps0;
            l1 = l1 * alpha1 + ps1;
            Asm[rg * 16 + lr] = alpha0;
            Asm[rg * 16 + lr + 8] = alpha1;
        }
        __syncthreads();

        // ---- rescale O, then O += P @ V (own d-half) ----
        float a0, a1;
        if (dh == 0) { a0 = alpha0; a1 = alpha1; }
        else         { a0 = Asm[rg * 16 + lr]; a1 = Asm[rg * 16 + lr + 8]; }
#pragma unroll
        for (int nf = 0; nf < 16; nf++) {
            oacc[nf][0] *= a0; oacc[nf][1] *= a0;
            oacc[nf][2] *= a1; oacc[nf][3] *= a1;
        }
        const __half* P = Psm + rg * 16 * PP;
#pragma unroll
        for (int kc = 0; kc < 4; kc++) {
            const int c0 = kc * 16 + 2 * lc;
            uint32_t a[4];
            a[0] = *(const uint32_t*)(P + lr * PP + c0);
            a[1] = *(const uint32_t*)(P + (lr + 8) * PP + c0);
            a[2] = *(const uint32_t*)(P + lr * PP + c0 + 8);
            a[3] = *(const uint32_t*)(P + (lr + 8) * PP + c0 + 8);
#pragma unroll
            for (int nf = 0; nf < 16; nf++) {
                int n = dh * 128 + nf * 8 + lr;
                uint32_t bb[2];
                bb[0] = *(const uint32_t*)(Vb + n * VP + c0);
                bb[1] = *(const uint32_t*)(Vb + n * VP + c0 + 8);
                MMA_F16(oacc[nf], a, bb);
            }
        }
    }

    // final 1/l
    if (dh == 0) {
        Lsm[rg * 16 + lr] = 1.f / l0;
        Lsm[rg * 16 + lr + 8] = 1.f / l1;
    }
    __syncthreads();
    const float inv0 = Lsm[rg * 16 + lr];
    const float inv1 = Lsm[rg * 16 + lr + 8];

#pragma unroll
    for (int nf = 0; nf < 16; nf++) {
        int col = h * HDc + dh * 128 + nf * 8 + 2 * lc;
        size_t r0a = (size_t)(b * Sc + q0 + rg * 16 + lr) * (Hc * HDc) + col;
        size_t r1a = (size_t)(b * Sc + q0 + rg * 16 + lr + 8) * (Hc * HDc) + col;
        *(__half2*)(ob + r0a) = __floats2half2_rn(oacc[nf][0] * inv0, oacc[nf][1] * inv0);
        *(__half2*)(ob + r1a) = __floats2half2_rn(oacc[nf][2] * inv1, oacc[nf][3] * inv1);
    }
}

// ---------------------------------------------------------------------------
extern "C" void kernel_launch(void* const* d_in, const int* in_sizes, int n_in,
                              void* d_out, int out_size)
{
    const float* hidden = (const float*)d_in[0];
    const float* Wq = (const float*)d_in[1];
    const float* Wk = (const float*)d_in[2];
    const float* Wv = (const float*)d_in[3];
    const float* Wo = (const float*)d_in[4];
    const float* qw = (const float*)d_in[5];
    const float* kw = (const float*)d_in[6];
    const int*  pos = (const int*)d_in[7];
    float* out = (float*)d_out;

    float *qb, *kb, *vb;
    __half *qhh, *khh, *vth, *ah, *hh, *wqT, *wkT, *wvT, *woT;
    cudaGetSymbolAddress((void**)&qb, g_q);
    cudaGetSymbolAddress((void**)&kb, g_k);
    cudaGetSymbolAddress((void**)&vb, g_v);
    cudaGetSymbolAddress((void**)&qhh, g_qh);
    cudaGetSymbolAddress((void**)&khh, g_kh);
    cudaGetSymbolAddress((void**)&vth, g_vt);
    cudaGetSymbolAddress((void**)&ah, g_attn_h);
    cudaGetSymbolAddress((void**)&hh, g_hh);
    cudaGetSymbolAddress((void**)&wqT, g_wqT);
    cudaGetSymbolAddress((void**)&wkT, g_wkT);
    cudaGetSymbolAddress((void**)&wvT, g_wvT);
    cudaGetSymbolAddress((void**)&woT, g_woT);

    const int M = Bc * Sc;           // 4096
    const int NQ = Hc * HDc;         // 4096
    const int NKV = KVc * HDc;       // 1024

    cudaFuncSetAttribute(gemm_f16, cudaFuncAttributeMaxDynamicSharedMemorySize, GEMM_SMEM);
    cudaFuncSetAttribute(flash_attn_tc, cudaFuncAttributeMaxDynamicSharedMemorySize, FLASH_SMEM);

    // Prep
    {
        int n4 = M * Dc / 4;
        to_half<<<(n4 + 255) / 256, 256>>>((const float4*)hidden, hh, n4);
    }
    transpose_half<<<dim3(NQ / 32, Dc / 32), 256>>>(Wq, wqT, Dc, NQ);
    transpose_half<<<dim3(NKV / 32, Dc / 32), 256>>>(Wk, wkT, Dc, NKV);
    transpose_half<<<dim3(NKV / 32, Dc / 32), 256>>>(Wv, wvT, Dc, NKV);
    transpose_half<<<dim3(Dc / 32, NQ / 32), 256>>>(Wo, woT, NQ, Dc);

    // QKV projections
    gemm_f16<<<dim3(NQ / BN, M / BM), 256, GEMM_SMEM>>>(hh, wqT, qb, M, NQ, Dc);
    gemm_f16<<<dim3(NKV / BN, M / BM), 256, GEMM_SMEM>>>(hh, wkT, kb, M, NKV, Dc);
    gemm_f16<<<dim3(NKV / BN, M / BM), 256, GEMM_SMEM>>>(hh, wvT, vb, M, NKV, Dc);

    // RMSNorm + RoPE -> fp16 head-major; V -> fp16 transposed
    rmsnorm_rope_h<<<M * Hc, 256>>>(qb, qhh, qw, pos, Hc);
    rmsnorm_rope_h<<<M * KVc, 256>>>(kb, khh, kw, pos, KVc);
    transpose_vt<<<dim3(HDc / 32, Sc / 32, Bc * KVc), 256>>>(vb, vth);

    // Tensor-core flash attention
    flash_attn_tc<<<dim3(Sc / 64, Hc, Bc), 256, FLASH_SMEM>>>(qhh, khh, vth, ah);

    // Output projection
    gemm_f16<<<dim3(Dc / BN, M / BM), 256, GEMM_SMEM>>>(ah, woT, out, M, Dc, NQ);
}

// round 7
// speedup vs baseline: 6.7436x; 1.0974x over previous
#include <cuda_runtime.h>
#include <cuda_fp16.h>
#include <cstdint>

// Problem constants (Gemma4 attention): B=2, S=2048, D=2048, H=16, KV=4, HD=256
#define Bc 2
#define Sc 2048
#define Dc 2048
#define Hc 16
#define KVc 4
#define HDc 256
#define NQKV 6144   // H*HD + 2*KV*HD

// Scratch (__device__ globals; no cudaMalloc allowed)
__device__ float  g_qkv[(size_t)Bc * Sc * NQKV];         // fused QKV out fp32
__device__ __half g_qh[(size_t)Bc * Hc * Sc * HDc];      // [b][h][s][d] fp16
__device__ __half g_kh[(size_t)Bc * KVc * Sc * HDc];     // [b][kv][s][d]
__device__ __half g_vt[(size_t)Bc * KVc * HDc * Sc];     // [b][kv][d][s]
__device__ __half g_attn_h[(size_t)Bc * Sc * Hc * HDc];  // [b,s][h*HD] fp16
__device__ __half g_hh[(size_t)Bc * Sc * Dc];            // hidden fp16
__device__ __half g_wqkvT[(size_t)NQKV * Dc];            // [6144][2048] fp16
__device__ __half g_woT[(size_t)Dc * (Hc * HDc)];        // [2048][4096]

// ===========================================================================
// Common PTX helpers
// ===========================================================================
__device__ __forceinline__ void cpasync16(const void* smem_dst, const void* gsrc) {
    uint32_t d = (uint32_t)__cvta_generic_to_shared(smem_dst);
    asm volatile("cp.async.cg.shared.global [%0], [%1], 16;" :: "r"(d), "l"(gsrc));
}
#define CP_COMMIT() asm volatile("cp.async.commit_group;" ::: "memory")
#define CP_WAIT0()  asm volatile("cp.async.wait_group 0;" ::: "memory")
#define CP_WAIT1()  asm volatile("cp.async.wait_group 1;" ::: "memory")

#define MMA_F16(d, a, b) \
    asm volatile("mma.sync.aligned.m16n8k16.row.col.f32.f16.f16.f32 " \
                 "{%0,%1,%2,%3}, {%4,%5,%6,%7}, {%8,%9}, {%0,%1,%2,%3};" \
                 : "+f"(d[0]), "+f"(d[1]), "+f"(d[2]), "+f"(d[3]) \
                 : "r"(a[0]), "r"(a[1]), "r"(a[2]), "r"(a[3]), \
                   "r"(b[0]), "r"(b[1]))

__device__ __forceinline__ void ldsm_x4(uint32_t* r, uint32_t saddr) {
    asm volatile("ldmatrix.sync.aligned.m8n8.x4.shared.b16 {%0,%1,%2,%3}, [%4];"
                 : "=r"(r[0]), "=r"(r[1]), "=r"(r[2]), "=r"(r[3]) : "r"(saddr));
}

// ===========================================================================
// fp16 mma.sync GEMM with ldmatrix fragment loads.
// C[M,N](fp32) = A[M,K](fp16) @ Bt[N,K](fp16)^T
// CTA 128x128, K-stage 64, 8 warps (2x4), warp tile 64x32, 2-stage cp.async.
// Smem pitch 72 halves (144B rows, 16B-aligned; ldmatrix conflict-free).
// ===========================================================================
#define BM 128
#define BN 128
#define BKH 64
#define PITCH 72
#define STAGE_HALF (2 * 128 * PITCH)
#define STAGE_BYTES (STAGE_HALF * 2)
#define GEMM_SMEM (2 * STAGE_BYTES)

__global__ __launch_bounds__(256, 2) void gemm_f16(
    const __half* __restrict__ A, const __half* __restrict__ Bt,
    float* __restrict__ C, int M, int N, int K)
{
    extern __shared__ __half smh[];
    const int tid = threadIdx.x;
    const int warp = tid >> 5, lane = tid & 31;
    const int wm = (warp >> 2) * 64, wn = (warp & 3) * 32;
    const int m0 = blockIdx.y * BM, n0 = blockIdx.x * BN;
    const int NT = K / BKH;

    // ldmatrix per-lane address components
    const int sel = lane >> 3, rr = lane & 7;
    const uint32_t sm0 = (uint32_t)__cvta_generic_to_shared(smh);
    // A: matrix sel: 0:(r,c0) 1:(r+8,c0) 2:(r,c0+8) 3:(r+8,c0+8)
    const uint32_t aOff = ((uint32_t)(wm + (sel & 1) * 8 + rr) * PITCH + (sel >> 1) * 8) * 2;
    // B: matrix sel: 0:(tn0,c0) 1:(tn0,c0+8) 2:(tn1,c0) 3:(tn1,c0+8)
    const uint32_t bOff = (uint32_t)(128 * PITCH) * 2 +
                          ((uint32_t)(wn + (sel >> 1) * 8 + rr) * PITCH + (sel & 1) * 8) * 2;

    float acc[4][4][4];
#pragma unroll
    for (int i = 0; i < 4; i++)
#pragma unroll
        for (int j = 0; j < 4; j++)
#pragma unroll
            for (int x = 0; x < 4; x++) acc[i][j][x] = 0.f;

    auto issue = [&](int kt) {
        __half* st = smh + (kt & 1) * STAGE_HALF;
        __half* As = st;
        __half* Bs = st + 128 * PITCH;
        const __half* Ag = A + (size_t)m0 * K + kt * BKH;
        const __half* Bg = Bt + (size_t)n0 * K + kt * BKH;
#pragma unroll
        for (int i = 0; i < 4; i++) {
            int idx = tid + i * 256;
            int r = idx >> 3, ch = idx & 7;
            cpasync16(As + r * PITCH + ch * 8, Ag + (size_t)r * K + ch * 8);
        }
#pragma unroll
        for (int i = 0; i < 4; i++) {
            int idx = tid + i * 256;
            int r = idx >> 3, ch = idx & 7;
            cpasync16(Bs + r * PITCH + ch * 8, Bg + (size_t)r * K + ch * 8);
        }
    };

    issue(0);
    CP_COMMIT();

    for (int kt = 0; kt < NT; kt++) {
        if (kt + 1 < NT) issue(kt + 1);
        CP_COMMIT();
        CP_WAIT1();
        __syncthreads();

        const uint32_t stage = sm0 + (kt & 1) * STAGE_BYTES;
        const uint32_t aBase = stage + aOff;
        const uint32_t bBase = stage + bOff;
#pragma unroll
        for (int kc = 0; kc < 4; kc++) {
            uint32_t a[4][4], b2[2][4];
#pragma unroll
            for (int tm = 0; tm < 4; tm++)
                ldsm_x4(a[tm], aBase + (uint32_t)(tm * 16 * PITCH) * 2 + kc * 32);
#pragma unroll
            for (int tp = 0; tp < 2; tp++)
                ldsm_x4(b2[tp], bBase + (uint32_t)(tp * 16 * PITCH) * 2 + kc * 32);
#pragma unroll
            for (int tm = 0; tm < 4; tm++)
#pragma unroll
                for (int tn = 0; tn < 4; tn++)
                    MMA_F16(acc[tm][tn], a[tm], (&b2[tn >> 1][(tn & 1) * 2]));
        }
        __syncthreads();
    }

#pragma unroll
    for (int tm = 0; tm < 4; tm++) {
#pragma unroll
        for (int tn = 0; tn < 4; tn++) {
            int row = m0 + wm + tm * 16 + (lane >> 2);
            int col = n0 + wn + tn * 8 + 2 * (lane & 3);
            *(float2*)(C + (size_t)row * N + col) =
                make_float2(acc[tm][tn][0], acc[tm][tn][1]);
            *(float2*)(C + (size_t)(row + 8) * N + col) =
                make_float2(acc[tm][tn][2], acc[tm][tn][3]);
        }
    }
}

// ---------------------------------------------------------------------------
// Prep kernels
// ---------------------------------------------------------------------------
__global__ __launch_bounds__(256) void to_half(const float4* __restrict__ src,
                                               __half* __restrict__ dst, int n4)
{
    int i = blockIdx.x * 256 + threadIdx.x;
    if (i < n4) {
        float4 v = src[i];
        __half2* d = (__half2*)(dst + (size_t)i * 4);
        d[0] = __floats2half2_rn(v.x, v.y);
        d[1] = __floats2half2_rn(v.z, v.w);
    }
}

__global__ __launch_bounds__(256) void transpose_half(
    const float* __restrict__ src, __half* __restrict__ dst, int R, int C)
{
    __shared__ float t[32][33];
    const int bx = blockIdx.x * 32;
    const int by = blockIdx.y * 32;
    const int x = threadIdx.x & 31;
    const int y0 = (threadIdx.x >> 5) * 4;
#pragma unroll
    for (int j = 0; j < 4; j++)
        t[y0 + j][x] = src[(size_t)(by + y0 + j) * C + bx + x];
    __syncthreads();
#pragma unroll
    for (int j = 0; j < 4; j++)
        dst[(size_t)(bx + y0 + j) * R + by + x] = __float2half_rn(t[x][y0 + j]);
}

// V slice of fused QKV fp32 -> Vt fp16 [b][kv][d][s]. v = qkv + 5120, stride 6144.
__global__ __launch_bounds__(256) void transpose_vt(
    const float* __restrict__ v, __half* __restrict__ vt)
{
    __shared__ float t[32][33];
    const int bkv = blockIdx.z;
    const int b = bkv >> 2, kv = bkv & 3;
    const int s0 = blockIdx.y * 32;
    const int d0 = blockIdx.x * 32;
    const int x = threadIdx.x & 31;
    const int y0 = (threadIdx.x >> 5) * 4;
#pragma unroll
    for (int j = 0; j < 4; j++)
        t[y0 + j][x] = v[(size_t)(b * Sc + s0 + y0 + j) * NQKV + kv * HDc + d0 + x];
    __syncthreads();
#pragma unroll
    for (int j = 0; j < 4; j++)
        vt[(size_t)(bkv * HDc + d0 + y0 + j) * Sc + s0 + x] = __float2half_rn(t[x][y0 + j]);
}

// ---------------------------------------------------------------------------
// RMSNorm + RoPE: fp32 slice of fused QKV (row stride NQKV) -> fp16 head-major.
// Fast math: exp2f for inv_freq, __sincosf for rotation.
// ---------------------------------------------------------------------------
__global__ __launch_bounds__(256) void rmsnorm_rope_h(
    const float* __restrict__ in, __half* __restrict__ outh,
    const float* __restrict__ w, const int* __restrict__ pos_ids, int nh)
{
    const int blk = blockIdx.x;           // (b*S+s)*nh + head
    const int d = threadIdx.x;
    const int head = blk % nh;
    const int bs = blk / nh;
    const int s = bs % Sc, b = bs / Sc;
    float v = in[(size_t)bs * NQKV + head * HDc + d];

    float sq = v * v;
#pragma unroll
    for (int o = 16; o; o >>= 1) sq += __shfl_xor_sync(0xffffffffu, sq, o);
    __shared__ float red[8];
    __shared__ float ys[256];
    if ((d & 31) == 0) red[d >> 5] = sq;
    __syncthreads();
    float tot = red[0] + red[1] + red[2] + red[3] + red[4] + red[5] + red[6] + red[7];
    float rstd = rsqrtf(tot * (1.0f / 256.0f) + 1e-6f);
    float y = v * rstd * (1.0f + w[d]);
    ys[d] = y;
    __syncthreads();
    float partner = (d < 128) ? -ys[d + 128] : ys[d - 128];

    float p = (float)pos_ids[s];
    // inv_freq = 10000^(-(d%128)/128) = exp2(-(d%128)*log2(10000)/128)
    float inv_freq = exp2f((float)(d & 127) * (-13.2877123795494f / 128.0f));
    float ang = p * inv_freq;
    float sv, cv;
    __sincosf(ang, &sv, &cv);
    outh[((size_t)(b * nh + head) * Sc + s) * HDc + d] =
        __float2half_rn(y * cv + partner * sv);
}

// ===========================================================================
// Tensor-core flash attention (unchanged from round 6; passing).
// ===========================================================================
#define QP 264
#define VP 72
#define SP 65
#define PP 72
#define OFF_KS (64 * QP)
#define OFF_VS (OFF_KS + 2 * 64 * QP)
#define OFF_SS ((OFF_VS + 2 * 256 * VP) * 2)
#define OFF_PS (OFF_SS + 4 * 16 * SP * 4)
#define OFF_AS (OFF_PS + 4 * 16 * PP * 2)
#define OFF_LS (OFF_AS + 64 * 4)
#define FLASH_SMEM (OFF_LS + 64 * 4)

__global__ __launch_bounds__(256, 1) void flash_attn_tc(
    const __half* __restrict__ qh, const __half* __restrict__ kh,
    const __half* __restrict__ vt, __half* __restrict__ ob)
{
    extern __shared__ char smc[];
    __half* Qs  = (__half*)smc;
    __half* Ks0 = Qs + OFF_KS;
    __half* Vs0 = Qs + OFF_VS;
    float*  Ssm = (float*)(smc + OFF_SS);
    __half* Psm = (__half*)(smc + OFF_PS);
    float*  Asm = (float*)(smc + OFF_AS);
    float*  Lsm = (float*)(smc + OFF_LS);

    const int qt = gridDim.x - 1 - blockIdx.x;
    const int q0 = qt * 64;
    const int h = blockIdx.y, b = blockIdx.z;
    const int kvh = h >> 2;
    const int tid = threadIdx.x;
    const int w = tid >> 5, lane = tid & 31;
    const int rg = w & 3, dh = w >> 2;
    const int lr = lane >> 2, lc = lane & 3;

    const __half* Qg = qh + ((size_t)(b * Hc + h) * Sc + q0) * HDc;
    const __half* Kg = kh + ((size_t)(b * KVc + kvh) * Sc) * HDc;
    const __half* Vg = vt + ((size_t)(b * KVc + kvh) * HDc) * Sc;

    auto issue_kv = [&](int t, int buf) {
        const int j0 = t * 64;
        __half* Kd = Ks0 + buf * 64 * QP;
        __half* Vd = Vs0 + buf * 256 * VP;
#pragma unroll
        for (int i = 0; i < 8; i++) {
            int idx = tid + i * 256;
            int r = idx >> 5, ch = idx & 31;
            cpasync16(Kd + r * QP + ch * 8, Kg + (size_t)(j0 + r) * HDc + ch * 8);
        }
#pragma unroll
        for (int i = 0; i < 8; i++) {
            int idx = tid + i * 256;
            int r = idx >> 3, ch = idx & 7;
            cpasync16(Vd + r * VP + ch * 8, Vg + (size_t)r * Sc + j0 + ch * 8);
        }
    };

#pragma unroll
    for (int i = 0; i < 8; i++) {
        int idx = tid + i * 256;
        int r = idx >> 5, ch = idx & 31;
        cpasync16(Qs + r * QP + ch * 8, Qg + (size_t)r * HDc + ch * 8);
    }
    issue_kv(0, 0);
    CP_COMMIT();

    float oacc[16][4];
#pragma unroll
    for (int i = 0; i < 16; i++)
#pragma unroll
        for (int j = 0; j < 4; j++) oacc[i][j] = 0.f;
    float m0v = -1e30f, m1v = -1e30f, l0 = 0.f, l1 = 0.f;
    float alpha0 = 1.f, alpha1 = 1.f;

    const int qg0 = q0 + rg * 16 + lr;
    const int qg1 = qg0 + 8;
    const int ntiles = q0 / 64 + 1;

    for (int t = 0; t < ntiles; t++) {
        CP_WAIT0();
        __syncthreads();
        if (t + 1 < ntiles) { issue_kv(t + 1, (t + 1) & 1); CP_COMMIT(); }

        const __half* Kb = Ks0 + (t & 1) * 64 * QP;
        const __half* Vb = Vs0 + (t & 1) * 256 * VP;
        const int j0 = t * 64;

        float sacc[8][4];
#pragma unroll
        for (int i = 0; i < 8; i++)
#pragma unroll
            for (int j = 0; j < 4; j++) sacc[i][j] = 0.f;
#pragma unroll
        for (int kc = 0; kc < 8; kc++) {
            const int c0 = dh * 128 + kc * 16 + 2 * lc;
            const int r = rg * 16 + lr;
            uint32_t a[4];
            a[0] = *(const uint32_t*)(Qs + r * QP + c0);
            a[1] = *(const uint32_t*)(Qs + (r + 8) * QP + c0);
            a[2] = *(const uint32_t*)(Qs + r * QP + c0 + 8);
            a[3] = *(const uint32_t*)(Qs + (r + 8) * QP + c0 + 8);
#pragma unroll
            for (int nf = 0; nf < 8; nf++) {
                int n = nf * 8 + lr;
                uint32_t bb[2];
                bb[0] = *(const uint32_t*)(Kb + n * QP + c0);
                bb[1] = *(const uint32_t*)(Kb + n * QP + c0 + 8);
                MMA_F16(sacc[nf], a, bb);
            }
        }

        if (dh == 1) {
            float* S = Ssm + rg * 16 * SP;
#pragma unroll
            for (int nf = 0; nf < 8; nf++) {
                int col = 8 * nf + 2 * lc;
                S[lr * SP + col]           = sacc[nf][0];
                S[lr * SP + col + 1]       = sacc[nf][1];
                S[(lr + 8) * SP + col]     = sacc[nf][2];
                S[(lr + 8) * SP + col + 1] = sacc[nf][3];
            }
        }
        __syncthreads();

        if (dh == 0) {
            const float* S = Ssm + rg * 16 * SP;
            const bool lastt = (t == ntiles - 1);
#pragma unroll
            for (int nf = 0; nf < 8; nf++) {
                int col = 8 * nf + 2 * lc;
                float s0 = (sacc[nf][0] + S[lr * SP + col]) * 0.0625f;
                float s1 = (sacc[nf][1] + S[lr * SP + col + 1]) * 0.0625f;
                float s2 = (sacc[nf][2] + S[(lr + 8) * SP + col]) * 0.0625f;
                float s3 = (sacc[nf][3] + S[(lr + 8) * SP + col + 1]) * 0.0625f;
                if (lastt) {
                    int j = j0 + col;
                    if (j > qg0)     s0 = -1e30f;
                    if (j + 1 > qg0) s1 = -1e30f;
                    if (j > qg1)     s2 = -1e30f;
                    if (j + 1 > qg1) s3 = -1e30f;
                }
                sacc[nf][0] = s0; sacc[nf][1] = s1; sacc[nf][2] = s2; sacc[nf][3] = s3;
            }
            float mx0 = -1e30f, mx1 = -1e30f;
#pragma unroll
            for (int nf = 0; nf < 8; nf++) {
                mx0 = fmaxf(mx0, fmaxf(sacc[nf][0], sacc[nf][1]));
                mx1 = fmaxf(mx1, fmaxf(sacc[nf][2], sacc[nf][3]));
            }
            mx0 = fmaxf(mx0, __shfl_xor_sync(0xffffffffu, mx0, 1));
            mx0 = fmaxf(mx0, __shfl_xor_sync(0xffffffffu, mx0, 2));
            mx1 = fmaxf(mx1, __shfl_xor_sync(0xffffffffu, mx1, 1));
            mx1 = fmaxf(mx1, __shfl_xor_sync(0xffffffffu, mx1, 2));
            float mn0 = fmaxf(m0v, mx0), mn1 = fmaxf(m1v, mx1);
            alpha0 = __expf(m0v - mn0);
            alpha1 = __expf(m1v - mn1);
            m0v = mn0; m1v = mn1;

            __half* P = Psm + rg * 16 * PP;
            float ps0 = 0.f, ps1 = 0.f;
#pragma unroll
            for (int nf = 0; nf < 8; nf++) {
                int col = 8 * nf + 2 * lc;
                float p0 = __expf(sacc[nf][0] - mn0);
                float p1 = __expf(sacc[nf][1] - mn0);
                float p2 = __expf(sacc[nf][2] - mn1);
                float p3 = __expf(sacc[nf][3] - mn1);
                ps0 += p0 + p1; ps1 += p2 + p3;
                *(__half2*)(P + lr * PP + col)       = __floats2half2_rn(p0, p1);
                *(__half2*)(P + (lr + 8) * PP + col) = __floats2half2_rn(p2, p3);
            }
            ps0 += __shfl_xor_sync(0xffffffffu, ps0, 1);
            ps0 += __shfl_xor_sync(0xffffffffu, ps0, 2);
            ps1 += __shfl_xor_sync(0xffffffffu, ps1, 1);
            ps1 += __shfl_xor_sync(0xffffffffu, ps1, 2);
            l0 = l0 * alpha0 + ps0;
            l1 = l1 * alpha1 + ps1;
            Asm[rg * 16 + lr] = alpha0;
            Asm[rg * 16 + lr + 8] = alpha1;
        }
        __syncthreads();

        float a0, a1;
        if (dh == 0) { a0 = alpha0; a1 = alpha1; }
        else         { a0 = Asm[rg * 16 + lr]; a1 = Asm[rg * 16 + lr + 8]; }
#pragma unroll
        for (int nf = 0; nf < 16; nf++) {
            oacc[nf][0] *= a0; oacc[nf][1] *= a0;
            oacc[nf][2] *= a1; oacc[nf][3] *= a1;
        }
        const __half* P = Psm + rg * 16 * PP;
#pragma unroll
        for (int kc = 0; kc < 4; kc++) {
            const int c0 = kc * 16 + 2 * lc;
            uint32_t a[4];
            a[0] = *(const uint32_t*)(P + lr * PP + c0);
            a[1] = *(const uint32_t*)(P + (lr + 8) * PP + c0);
            a[2] = *(const uint32_t*)(P + lr * PP + c0 + 8);
            a[3] = *(const uint32_t*)(P + (lr + 8) * PP + c0 + 8);
#pragma unroll
            for (int nf = 0; nf < 16; nf++) {
                int n = dh * 128 + nf * 8 + lr;
                uint32_t bb[2];
                bb[0] = *(const uint32_t*)(Vb + n * VP + c0);
                bb[1] = *(const uint32_t*)(Vb + n * VP + c0 + 8);
                MMA_F16(oacc[nf], a, bb);
            }
        }
    }

    if (dh == 0) {
        Lsm[rg * 16 + lr] = 1.f / l0;
        Lsm[rg * 16 + lr + 8] = 1.f / l1;
    }
    __syncthreads();
    const float inv0 = Lsm[rg * 16 + lr];
    const float inv1 = Lsm[rg * 16 + lr + 8];

#pragma unroll
    for (int nf = 0; nf < 16; nf++) {
        int col = h * HDc + dh * 128 + nf * 8 + 2 * lc;
        size_t r0a = (size_t)(b * Sc + q0 + rg * 16 + lr) * (Hc * HDc) + col;
        size_t r1a = (size_t)(b * Sc + q0 + rg * 16 + lr + 8) * (Hc * HDc) + col;
        *(__half2*)(ob + r0a) = __floats2half2_rn(oacc[nf][0] * inv0, oacc[nf][1] * inv0);
        *(__half2*)(ob + r1a) = __floats2half2_rn(oacc[nf][2] * inv1, oacc[nf][3] * inv1);
    }
}

// ---------------------------------------------------------------------------
extern "C" void kernel_launch(void* const* d_in, const int* in_sizes, int n_in,
                              void* d_out, int out_size)
{
    const float* hidden = (const float*)d_in[0];
    const float* Wq = (const float*)d_in[1];
    const float* Wk = (const float*)d_in[2];
    const float* Wv = (const float*)d_in[3];
    const float* Wo = (const float*)d_in[4];
    const float* qw = (const float*)d_in[5];
    const float* kw = (const float*)d_in[6];
    const int*  pos = (const int*)d_in[7];
    float* out = (float*)d_out;

    float *qkvb;
    __half *qhh, *khh, *vth, *ah, *hh, *wqkvT, *woT;
    cudaGetSymbolAddress((void**)&qkvb, g_qkv);
    cudaGetSymbolAddress((void**)&qhh, g_qh);
    cudaGetSymbolAddress((void**)&khh, g_kh);
    cudaGetSymbolAddress((void**)&vth, g_vt);
    cudaGetSymbolAddress((void**)&ah, g_attn_h);
    cudaGetSymbolAddress((void**)&hh, g_hh);
    cudaGetSymbolAddress((void**)&wqkvT, g_wqkvT);
    cudaGetSymbolAddress((void**)&woT, g_woT);

    const int M = Bc * Sc;           // 4096
    const int NQ = Hc * HDc;         // 4096
    const int NKV = KVc * HDc;       // 1024

    cudaFuncSetAttribute(gemm_f16, cudaFuncAttributeMaxDynamicSharedMemorySize, GEMM_SMEM);
    cudaFuncSetAttribute(flash_attn_tc, cudaFuncAttributeMaxDynamicSharedMemorySize, FLASH_SMEM);

    // Prep: hidden -> fp16; weights -> fused transposed fp16 [6144][2048] + Wo
    {
        int n4 = M * Dc / 4;
        to_half<<<(n4 + 255) / 256, 256>>>((const float4*)hidden, hh, n4);
    }
    transpose_half<<<dim3(NQ / 32, Dc / 32), 256>>>(Wq, wqkvT, Dc, NQ);
    transpose_half<<<dim3(NKV / 32, Dc / 32), 256>>>(Wk, wqkvT + (size_t)NQ * Dc, Dc, NKV);
    transpose_half<<<dim3(NKV / 32, Dc / 32), 256>>>(Wv, wqkvT + (size_t)(NQ + NKV) * Dc, Dc, NKV);
    transpose_half<<<dim3(Dc / 32, NQ / 32), 256>>>(Wo, woT, NQ, Dc);

    // Fused QKV projection (one launch, N=6144)
    gemm_f16<<<dim3(NQKV / BN, M / BM), 256, GEMM_SMEM>>>(hh, wqkvT, qkvb, M, NQKV, Dc);

    // RMSNorm + RoPE -> fp16 head-major; V slice -> fp16 transposed
    rmsnorm_rope_h<<<M * Hc, 256>>>(qkvb, qhh, qw, pos, Hc);
    rmsnorm_rope_h<<<M * KVc, 256>>>(qkvb + NQ, khh, kw, pos, KVc);
    transpose_vt<<<dim3(HDc / 32, Sc / 32, Bc * KVc), 256>>>(qkvb + NQ + NKV, vth);

    // Tensor-core flash attention
    flash_attn_tc<<<dim3(Sc / 64, Hc, Bc), 256, FLASH_SMEM>>>(qhh, khh, vth, ah);

    // Output projection
    gemm_f16<<<dim3(Dc / BN, M / BM), 256, GEMM_SMEM>>>(ah, woT, out, M, Dc, NQ);
}

// round 8
// speedup vs baseline: 7.7170x; 1.1443x over previous
#include <cuda_runtime.h>
#include <cuda_fp16.h>
#include <cstdint>

// Problem constants (Gemma4 attention): B=2, S=2048, D=2048, H=16, KV=4, HD=256
#define Bc 2
#define Sc 2048
#define Dc 2048
#define Hc 16
#define KVc 4
#define HDc 256
#define NQKV 6144   // H*HD + 2*KV*HD

// Scratch (__device__ globals; no cudaMalloc allowed)
__device__ __half g_qkvh[(size_t)Bc * Sc * NQKV];        // fused QKV out fp16
__device__ __half g_qh[(size_t)Bc * Hc * Sc * HDc];      // [b][h][s][d] (pre-scaled 1/16)
__device__ __half g_kh[(size_t)Bc * KVc * Sc * HDc];     // [b][kv][s][d]
__device__ __half g_vt[(size_t)Bc * KVc * HDc * Sc];     // [b][kv][d][s]
__device__ __half g_attn_h[(size_t)Bc * Sc * Hc * HDc];  // [b,s][h*HD] fp16
__device__ __half g_hh[(size_t)Bc * Sc * Dc];            // hidden fp16
__device__ __half g_wqkvT[(size_t)NQKV * Dc];            // [6144][2048] fp16
__device__ __half g_woT[(size_t)Dc * (Hc * HDc)];        // [2048][4096]

// ===========================================================================
// Common PTX helpers
// ===========================================================================
__device__ __forceinline__ void cpasync16(const void* smem_dst, const void* gsrc) {
    uint32_t d = (uint32_t)__cvta_generic_to_shared(smem_dst);
    asm volatile("cp.async.cg.shared.global [%0], [%1], 16;" :: "r"(d), "l"(gsrc));
}
#define CP_COMMIT() asm volatile("cp.async.commit_group;" ::: "memory")
#define CP_WAIT0()  asm volatile("cp.async.wait_group 0;" ::: "memory")
#define CP_WAIT1()  asm volatile("cp.async.wait_group 1;" ::: "memory")

#define MMA_F16(d, a, b) \
    asm volatile("mma.sync.aligned.m16n8k16.row.col.f32.f16.f16.f32 " \
                 "{%0,%1,%2,%3}, {%4,%5,%6,%7}, {%8,%9}, {%0,%1,%2,%3};" \
                 : "+f"(d[0]), "+f"(d[1]), "+f"(d[2]), "+f"(d[3]) \
                 : "r"(a[0]), "r"(a[1]), "r"(a[2]), "r"(a[3]), \
                   "r"(b[0]), "r"(b[1]))

__device__ __forceinline__ void ldsm_x4(uint32_t* r, uint32_t saddr) {
    asm volatile("ldmatrix.sync.aligned.m8n8.x4.shared.b16 {%0,%1,%2,%3}, [%4];"
                 : "=r"(r[0]), "=r"(r[1]), "=r"(r[2]), "=r"(r[3]) : "r"(saddr));
}
__device__ __forceinline__ uint32_t packh2(float a, float b) {
    __half2 h = __floats2half2_rn(a, b);
    return *(uint32_t*)&h;
}

// ===========================================================================
// fp16 mma.sync GEMM with ldmatrix; templated output type (fp16 or fp32).
// C[M,N] = A[M,K](fp16) @ Bt[N,K](fp16)^T
// ===========================================================================
#define BM 128
#define BN 128
#define BKH 64
#define PITCH 72
#define STAGE_HALF (2 * 128 * PITCH)
#define STAGE_BYTES (STAGE_HALF * 2)
#define GEMM_SMEM (2 * STAGE_BYTES)

template <typename OT>
__global__ __launch_bounds__(256, 2) void gemm_f16(
    const __half* __restrict__ A, const __half* __restrict__ Bt,
    OT* __restrict__ C, int M, int N, int K)
{
    extern __shared__ __half smh[];
    const int tid = threadIdx.x;
    const int warp = tid >> 5, lane = tid & 31;
    const int wm = (warp >> 2) * 64, wn = (warp & 3) * 32;
    const int m0 = blockIdx.y * BM, n0 = blockIdx.x * BN;
    const int NT = K / BKH;

    const int sel = lane >> 3, rr = lane & 7;
    const uint32_t sm0 = (uint32_t)__cvta_generic_to_shared(smh);
    const uint32_t aOff = ((uint32_t)(wm + (sel & 1) * 8 + rr) * PITCH + (sel >> 1) * 8) * 2;
    const uint32_t bOff = (uint32_t)(128 * PITCH) * 2 +
                          ((uint32_t)(wn + (sel >> 1) * 8 + rr) * PITCH + (sel & 1) * 8) * 2;

    float acc[4][4][4];
#pragma unroll
    for (int i = 0; i < 4; i++)
#pragma unroll
        for (int j = 0; j < 4; j++)
#pragma unroll
            for (int x = 0; x < 4; x++) acc[i][j][x] = 0.f;

    auto issue = [&](int kt) {
        __half* st = smh + (kt & 1) * STAGE_HALF;
        __half* As = st;
        __half* Bs = st + 128 * PITCH;
        const __half* Ag = A + (size_t)m0 * K + kt * BKH;
        const __half* Bg = Bt + (size_t)n0 * K + kt * BKH;
#pragma unroll
        for (int i = 0; i < 4; i++) {
            int idx = tid + i * 256;
            int r = idx >> 3, ch = idx & 7;
            cpasync16(As + r * PITCH + ch * 8, Ag + (size_t)r * K + ch * 8);
        }
#pragma unroll
        for (int i = 0; i < 4; i++) {
            int idx = tid + i * 256;
            int r = idx >> 3, ch = idx & 7;
            cpasync16(Bs + r * PITCH + ch * 8, Bg + (size_t)r * K + ch * 8);
        }
    };

    issue(0);
    CP_COMMIT();

    for (int kt = 0; kt < NT; kt++) {
        if (kt + 1 < NT) issue(kt + 1);
        CP_COMMIT();
        CP_WAIT1();
        __syncthreads();

        const uint32_t stage = sm0 + (kt & 1) * STAGE_BYTES;
        const uint32_t aBase = stage + aOff;
        const uint32_t bBase = stage + bOff;
#pragma unroll
        for (int kc = 0; kc < 4; kc++) {
            uint32_t a[4][4], b2[2][4];
#pragma unroll
            for (int tm = 0; tm < 4; tm++)
                ldsm_x4(a[tm], aBase + (uint32_t)(tm * 16 * PITCH) * 2 + kc * 32);
#pragma unroll
            for (int tp = 0; tp < 2; tp++)
                ldsm_x4(b2[tp], bBase + (uint32_t)(tp * 16 * PITCH) * 2 + kc * 32);
#pragma unroll
            for (int tm = 0; tm < 4; tm++)
#pragma unroll
                for (int tn = 0; tn < 4; tn++)
                    MMA_F16(acc[tm][tn], a[tm], (&b2[tn >> 1][(tn & 1) * 2]));
        }
        __syncthreads();
    }

#pragma unroll
    for (int tm = 0; tm < 4; tm++) {
#pragma unroll
        for (int tn = 0; tn < 4; tn++) {
            int row = m0 + wm + tm * 16 + (lane >> 2);
            int col = n0 + wn + tn * 8 + 2 * (lane & 3);
            if constexpr (sizeof(OT) == 2) {
                *(__half2*)((__half*)C + (size_t)row * N + col) =
                    __floats2half2_rn(acc[tm][tn][0], acc[tm][tn][1]);
                *(__half2*)((__half*)C + (size_t)(row + 8) * N + col) =
                    __floats2half2_rn(acc[tm][tn][2], acc[tm][tn][3]);
            } else {
                *(float2*)((float*)C + (size_t)row * N + col) =
                    make_float2(acc[tm][tn][0], acc[tm][tn][1]);
                *(float2*)((float*)C + (size_t)(row + 8) * N + col) =
                    make_float2(acc[tm][tn][2], acc[tm][tn][3]);
            }
        }
    }
}

// ---------------------------------------------------------------------------
// Prep kernels
// ---------------------------------------------------------------------------
__global__ __launch_bounds__(256) void to_half(const float4* __restrict__ src,
                                               __half* __restrict__ dst, int n4)
{
    int i = blockIdx.x * 256 + threadIdx.x;
    if (i < n4) {
        float4 v = src[i];
        __half2* d = (__half2*)(dst + (size_t)i * 4);
        d[0] = __floats2half2_rn(v.x, v.y);
        d[1] = __floats2half2_rn(v.z, v.w);
    }
}

__global__ __launch_bounds__(256) void transpose_half(
    const float* __restrict__ src, __half* __restrict__ dst, int R, int C)
{
    __shared__ float t[32][33];
    const int bx = blockIdx.x * 32;
    const int by = blockIdx.y * 32;
    const int x = threadIdx.x & 31;
    const int y0 = (threadIdx.x >> 5) * 4;
#pragma unroll
    for (int j = 0; j < 4; j++)
        t[y0 + j][x] = src[(size_t)(by + y0 + j) * C + bx + x];
    __syncthreads();
#pragma unroll
    for (int j = 0; j < 4; j++)
        dst[(size_t)(bx + y0 + j) * R + by + x] = __float2half_rn(t[x][y0 + j]);
}

// V slice of fused QKV fp16 (row stride NQKV) -> Vt fp16 [b][kv][d][s]
__global__ __launch_bounds__(256) void transpose_vt(
    const __half* __restrict__ v, __half* __restrict__ vt)
{
    __shared__ __half t[32][34];
    const int bkv = blockIdx.z;
    const int b = bkv >> 2, kv = bkv & 3;
    const int s0 = blockIdx.y * 32;
    const int d0 = blockIdx.x * 32;
    const int x = threadIdx.x & 31;
    const int y0 = (threadIdx.x >> 5) * 4;
#pragma unroll
    for (int j = 0; j < 4; j++)
        t[y0 + j][x] = v[(size_t)(b * Sc + s0 + y0 + j) * NQKV + kv * HDc + d0 + x];
    __syncthreads();
#pragma unroll
    for (int j = 0; j < 4; j++)
        vt[(size_t)(bkv * HDc + d0 + y0 + j) * Sc + s0 + x] = t[x][y0 + j];
}

// ---------------------------------------------------------------------------
// RMSNorm + RoPE: fp16 slice of fused QKV (row stride NQKV) -> fp16 head-major,
// output multiplied by oscale (attention scale folded into Q).
// ---------------------------------------------------------------------------
__global__ __launch_bounds__(256) void rmsnorm_rope_h(
    const __half* __restrict__ in, __half* __restrict__ outh,
    const float* __restrict__ w, const int* __restrict__ pos_ids, int nh,
    float oscale)
{
    const int blk = blockIdx.x;           // (b*S+s)*nh + head
    const int d = threadIdx.x;
    const int head = blk % nh;
    const int bs = blk / nh;
    const int s = bs % Sc, b = bs / Sc;
    float v = __half2float(in[(size_t)bs * NQKV + head * HDc + d]);

    float sq = v * v;
#pragma unroll
    for (int o = 16; o; o >>= 1) sq += __shfl_xor_sync(0xffffffffu, sq, o);
    __shared__ float red[8];
    __shared__ float ys[256];
    if ((d & 31) == 0) red[d >> 5] = sq;
    __syncthreads();
    float tot = red[0] + red[1] + red[2] + red[3] + red[4] + red[5] + red[6] + red[7];
    float rstd = rsqrtf(tot * (1.0f / 256.0f) + 1e-6f);
    float y = v * rstd * (1.0f + w[d]);
    ys[d] = y;
    __syncthreads();
    float partner = (d < 128) ? -ys[d + 128] : ys[d - 128];

    float p = (float)pos_ids[s];
    float inv_freq = exp2f((float)(d & 127) * (-13.2877123795494f / 128.0f));
    float ang = p * inv_freq;
    float sv, cv;
    __sincosf(ang, &sv, &cv);
    outh[((size_t)(b * nh + head) * Sc + s) * HDc + d] =
        __float2half_rn((y * cv + partner * sv) * oscale);
}

// ===========================================================================
// FA2-style tensor-core flash attention.
// CTA = 128 q rows, 8 warps; warp owns 16 rows x full d=256.
// S/softmax/P all in registers; only K/V double-buffer syncs remain.
// Q pre-scaled by 1/16. Key tiles of 64, ldmatrix everywhere.
// ===========================================================================
#define FQP 264   // halves pitch for Q and K rows (256 d + 8)
#define FVP 72    // halves pitch for Vt rows (64 s + 8)
#define F_KS (128 * FQP)                 // halves offset of K bufs
#define F_VS (F_KS + 2 * 64 * FQP)       // halves offset of V bufs
#define FLASH_SMEM ((F_VS + 2 * 256 * FVP) * 2)   // 208896 bytes

__global__ __launch_bounds__(256, 1) void flash_attn_tc(
    const __half* __restrict__ qh, const __half* __restrict__ kh,
    const __half* __restrict__ vt, __half* __restrict__ ob)
{
    extern __shared__ __half sm[];
    __half* Qs  = sm;
    __half* Ks0 = sm + F_KS;
    __half* Vs0 = sm + F_VS;

    const int qt = gridDim.x - 1 - blockIdx.x;   // heavy tiles first
    const int q0 = qt * 128;
    const int h = blockIdx.y, b = blockIdx.z;
    const int kvh = h >> 2;
    const int tid = threadIdx.x;
    const int w = tid >> 5, lane = tid & 31;
    const int lr = lane >> 2, lc = lane & 3;
    const int sel = lane >> 3, rr = lane & 7;

    const __half* Qg = qh + ((size_t)(b * Hc + h) * Sc + q0) * HDc;
    const __half* Kg = kh + ((size_t)(b * KVc + kvh) * Sc) * HDc;
    const __half* Vg = vt + ((size_t)(b * KVc + kvh) * HDc) * Sc;

    auto issue_kv = [&](int t, int buf) {
        const int j0 = t * 64;
        __half* Kd = Ks0 + buf * 64 * FQP;
        __half* Vd = Vs0 + buf * 256 * FVP;
#pragma unroll
        for (int i = 0; i < 8; i++) {          // K: 64 rows x 32 16B-chunks
            int idx = tid + i * 256;
            int r = idx >> 5, ch = idx & 31;
            cpasync16(Kd + r * FQP + ch * 8, Kg + (size_t)(j0 + r) * HDc + ch * 8);
        }
#pragma unroll
        for (int i = 0; i < 8; i++) {          // Vt: 256 rows x 8 chunks
            int idx = tid + i * 256;
            int r = idx >> 3, ch = idx & 7;
            cpasync16(Vd + r * FVP + ch * 8, Vg + (size_t)r * Sc + j0 + ch * 8);
        }
    };

    // Q tile: 128 rows x 32 chunks = 4096 -> 16 per thread
#pragma unroll
    for (int i = 0; i < 16; i++) {
        int idx = tid + i * 256;
        int r = idx >> 5, ch = idx & 31;
        cpasync16(Qs + r * FQP + ch * 8, Qg + (size_t)r * HDc + ch * 8);
    }
    issue_kv(0, 0);
    CP_COMMIT();

    // ldmatrix per-lane bases
    const uint32_t smb = (uint32_t)__cvta_generic_to_shared(sm);
    const uint32_t qA   = smb + ((uint32_t)(w * 16 + (sel & 1) * 8 + rr) * FQP + (sel >> 1) * 8) * 2;
    const uint32_t kOff = ((uint32_t)((sel >> 1) * 8 + rr) * FQP + (sel & 1) * 8) * 2;
    const uint32_t vOff = ((uint32_t)((sel >> 1) * 8 + rr) * FVP + (sel & 1) * 8) * 2;

    float oacc[32][4];
#pragma unroll
    for (int i = 0; i < 32; i++)
#pragma unroll
        for (int j = 0; j < 4; j++) oacc[i][j] = 0.f;
    float m0v = -1e30f, m1v = -1e30f, l0 = 0.f, l1 = 0.f;

    const int qg0 = q0 + w * 16 + lr;
    const int qg1 = qg0 + 8;
    const int qmaxw = q0 + w * 16 + 15;
    const int ntiles = q0 / 64 + 2;

    for (int t = 0; t < ntiles; t++) {
        CP_WAIT0();
        __syncthreads();
        if (t + 1 < ntiles) { issue_kv(t + 1, (t + 1) & 1); CP_COMMIT(); }
        const int j0 = t * 64;

        if (j0 <= qmaxw) {   // tile intersects this warp's causal range
            const uint32_t kB = smb + (uint32_t)(F_KS + (t & 1) * 64 * FQP) * 2 + kOff;
            const uint32_t vB = smb + (uint32_t)(F_VS + (t & 1) * 256 * FVP) * 2 + vOff;

            // ---- S = Q @ K^T (16 x 64), in regs ----
            float sacc[8][4];
#pragma unroll
            for (int i = 0; i < 8; i++)
#pragma unroll
                for (int j = 0; j < 4; j++) sacc[i][j] = 0.f;
#pragma unroll
            for (int kc = 0; kc < 16; kc++) {
                uint32_t a[4];
                ldsm_x4(a, qA + kc * 32);
#pragma unroll
                for (int tp = 0; tp < 4; tp++) {
                    uint32_t bb[4];
                    ldsm_x4(bb, kB + (uint32_t)(tp * 16 * FQP) * 2 + kc * 32);
                    MMA_F16(sacc[2 * tp], a, (&bb[0]));
                    MMA_F16(sacc[2 * tp + 1], a, (&bb[2]));
                }
            }

            // ---- causal mask (only near diagonal) ----
            if (j0 + 63 > q0 + w * 16) {
#pragma unroll
                for (int nf = 0; nf < 8; nf++) {
                    int j = j0 + 8 * nf + 2 * lc;
                    if (j > qg0)     sacc[nf][0] = -1e30f;
                    if (j + 1 > qg0) sacc[nf][1] = -1e30f;
                    if (j > qg1)     sacc[nf][2] = -1e30f;
                    if (j + 1 > qg1) sacc[nf][3] = -1e30f;
                }
            }

            // ---- online softmax (in-warp; rows lr and lr+8) ----
            float mx0 = -1e30f, mx1 = -1e30f;
#pragma unroll
            for (int nf = 0; nf < 8; nf++) {
                mx0 = fmaxf(mx0, fmaxf(sacc[nf][0], sacc[nf][1]));
                mx1 = fmaxf(mx1, fmaxf(sacc[nf][2], sacc[nf][3]));
            }
            mx0 = fmaxf(mx0, __shfl_xor_sync(0xffffffffu, mx0, 1));
            mx0 = fmaxf(mx0, __shfl_xor_sync(0xffffffffu, mx0, 2));
            mx1 = fmaxf(mx1, __shfl_xor_sync(0xffffffffu, mx1, 1));
            mx1 = fmaxf(mx1, __shfl_xor_sync(0xffffffffu, mx1, 2));
            float mn0 = fmaxf(m0v, mx0), mn1 = fmaxf(m1v, mx1);
            float alpha0 = __expf(m0v - mn0);
            float alpha1 = __expf(m1v - mn1);
            m0v = mn0; m1v = mn1;

            float ps0 = 0.f, ps1 = 0.f;
#pragma unroll
            for (int nf = 0; nf < 8; nf++) {
                sacc[nf][0] = __expf(sacc[nf][0] - mn0);
                sacc[nf][1] = __expf(sacc[nf][1] - mn0);
                sacc[nf][2] = __expf(sacc[nf][2] - mn1);
                sacc[nf][3] = __expf(sacc[nf][3] - mn1);
                ps0 += sacc[nf][0] + sacc[nf][1];
                ps1 += sacc[nf][2] + sacc[nf][3];
            }
            ps0 += __shfl_xor_sync(0xffffffffu, ps0, 1);
            ps0 += __shfl_xor_sync(0xffffffffu, ps0, 2);
            ps1 += __shfl_xor_sync(0xffffffffu, ps1, 1);
            ps1 += __shfl_xor_sync(0xffffffffu, ps1, 2);
            l0 = l0 * alpha0 + ps0;
            l1 = l1 * alpha1 + ps1;

#pragma unroll
            for (int nf = 0; nf < 32; nf++) {
                oacc[nf][0] *= alpha0; oacc[nf][1] *= alpha0;
                oacc[nf][2] *= alpha1; oacc[nf][3] *= alpha1;
            }

            // ---- O += P @ V (P packed from sacc; V frags via ldmatrix) ----
#pragma unroll
            for (int kc = 0; kc < 4; kc++) {
                uint32_t pa[4];
                pa[0] = packh2(sacc[2 * kc][0],     sacc[2 * kc][1]);
                pa[1] = packh2(sacc[2 * kc][2],     sacc[2 * kc][3]);
                pa[2] = packh2(sacc[2 * kc + 1][0], sacc[2 * kc + 1][1]);
                pa[3] = packh2(sacc[2 * kc + 1][2], sacc[2 * kc + 1][3]);
#pragma unroll
                for (int tp = 0; tp < 16; tp++) {
                    uint32_t bb[4];
                    ldsm_x4(bb, vB + (uint32_t)(tp * 16 * FVP) * 2 + kc * 32);
                    MMA_F16(oacc[2 * tp], pa, (&bb[0]));
                    MMA_F16(oacc[2 * tp + 1], pa, (&bb[2]));
                }
            }
        }
    }

    // Epilogue: out = oacc / l, fp16, layout [b,s][h*HD]
    const float inv0 = 1.f / l0;
    const float inv1 = 1.f / l1;
#pragma unroll
    for (int nf = 0; nf < 32; nf++) {
        int col = h * HDc + 8 * nf + 2 * lc;
        size_t r0a = (size_t)(b * Sc + q0 + w * 16 + lr) * (Hc * HDc) + col;
        size_t r1a = (size_t)(b * Sc + q0 + w * 16 + lr + 8) * (Hc * HDc) + col;
        *(__half2*)(ob + r0a) = __floats2half2_rn(oacc[nf][0] * inv0, oacc[nf][1] * inv0);
        *(__half2*)(ob + r1a) = __floats2half2_rn(oacc[nf][2] * inv1, oacc[nf][3] * inv1);
    }
}

// ---------------------------------------------------------------------------
extern "C" void kernel_launch(void* const* d_in, const int* in_sizes, int n_in,
                              void* d_out, int out_size)
{
    const float* hidden = (const float*)d_in[0];
    const float* Wq = (const float*)d_in[1];
    const float* Wk = (const float*)d_in[2];
    const float* Wv = (const float*)d_in[3];
    const float* Wo = (const float*)d_in[4];
    const float* qw = (const float*)d_in[5];
    const float* kw = (const float*)d_in[6];
    const int*  pos = (const int*)d_in[7];
    float* out = (float*)d_out;

    __half *qkvh, *qhh, *khh, *vth, *ah, *hh, *wqkvT, *woT;
    cudaGetSymbolAddress((void**)&qkvh, g_qkvh);
    cudaGetSymbolAddress((void**)&qhh, g_qh);
    cudaGetSymbolAddress((void**)&khh, g_kh);
    cudaGetSymbolAddress((void**)&vth, g_vt);
    cudaGetSymbolAddress((void**)&ah, g_attn_h);
    cudaGetSymbolAddress((void**)&hh, g_hh);
    cudaGetSymbolAddress((void**)&wqkvT, g_wqkvT);
    cudaGetSymbolAddress((void**)&woT, g_woT);

    const int M = Bc * Sc;           // 4096
    const int NQ = Hc * HDc;         // 4096
    const int NKV = KVc * HDc;       // 1024

    cudaFuncSetAttribute(gemm_f16<__half>, cudaFuncAttributeMaxDynamicSharedMemorySize, GEMM_SMEM);
    cudaFuncSetAttribute(gemm_f16<float>, cudaFuncAttributeMaxDynamicSharedMemorySize, GEMM_SMEM);
    cudaFuncSetAttribute(flash_attn_tc, cudaFuncAttributeMaxDynamicSharedMemorySize, FLASH_SMEM);

    // Prep: hidden -> fp16; weights -> fused transposed fp16 + Wo
    {
        int n4 = M * Dc / 4;
        to_half<<<(n4 + 255) / 256, 256>>>((const float4*)hidden, hh, n4);
    }
    transpose_half<<<dim3(NQ / 32, Dc / 32), 256>>>(Wq, wqkvT, Dc, NQ);
    transpose_half<<<dim3(NKV / 32, Dc / 32), 256>>>(Wk, wqkvT + (size_t)NQ * Dc, Dc, NKV);
    transpose_half<<<dim3(NKV / 32, Dc / 32), 256>>>(Wv, wqkvT + (size_t)(NQ + NKV) * Dc, Dc, NKV);
    transpose_half<<<dim3(Dc / 32, NQ / 32), 256>>>(Wo, woT, NQ, Dc);

    // Fused QKV projection -> fp16
    gemm_f16<__half><<<dim3(NQKV / BN, M / BM), 256, GEMM_SMEM>>>(hh, wqkvT, qkvh, M, NQKV, Dc);

    // RMSNorm + RoPE -> fp16 head-major (Q pre-scaled by 1/16); V -> transposed
    rmsnorm_rope_h<<<M * Hc, 256>>>(qkvh, qhh, qw, pos, Hc, 0.0625f);
    rmsnorm_rope_h<<<M * KVc, 256>>>(qkvh + NQ, khh, kw, pos, KVc, 1.0f);
    transpose_vt<<<dim3(HDc / 32, Sc / 32, Bc * KVc), 256>>>(qkvh + NQ + NKV, vth);

    // FA2-style tensor-core flash attention
    flash_attn_tc<<<dim3(Sc / 128, Hc, Bc), 256, FLASH_SMEM>>>(qhh, khh, vth, ah);

    // Output projection -> fp32
    gemm_f16<float><<<dim3(Dc / BN, M / BM), 256, GEMM_SMEM>>>(ah, woT, out, M, Dc, NQ);
}

// round 9
// speedup vs baseline: 7.7691x; 1.0067x over previous
#include <cuda_runtime.h>
#include <cuda_fp16.h>
#include <cstdint>

// Problem constants (Gemma4 attention): B=2, S=2048, D=2048, H=16, KV=4, HD=256
#define Bc 2
#define Sc 2048
#define Dc 2048
#define Hc 16
#define KVc 4
#define HDc 256
#define NQKV 6144   // H*HD + 2*KV*HD

// Scratch (__device__ globals; no cudaMalloc allowed)
__device__ __half g_qkvh[(size_t)Bc * Sc * NQKV];        // fused QKV out fp16
__device__ __half g_qh[(size_t)Bc * Hc * Sc * HDc];      // [b][h][s][d] (pre-scaled 1/16)
__device__ __half g_kh[(size_t)Bc * KVc * Sc * HDc];     // [b][kv][s][d]
__device__ __half g_vt[(size_t)Bc * KVc * HDc * Sc];     // [b][kv][d][s]
__device__ __half g_attn_h[(size_t)Bc * Sc * Hc * HDc];  // [b,s][h*HD] fp16
__device__ __half g_hh[(size_t)Bc * Sc * Dc];            // hidden fp16
__device__ __half g_wqkvT[(size_t)NQKV * Dc];            // [6144][2048] fp16
__device__ __half g_woT[(size_t)Dc * (Hc * HDc)];        // [2048][4096]

// ===========================================================================
// Common PTX helpers
// ===========================================================================
__device__ __forceinline__ void cpasync16(const void* smem_dst, const void* gsrc) {
    uint32_t d = (uint32_t)__cvta_generic_to_shared(smem_dst);
    asm volatile("cp.async.cg.shared.global [%0], [%1], 16;" :: "r"(d), "l"(gsrc));
}
#define CP_COMMIT() asm volatile("cp.async.commit_group;" ::: "memory")
#define CP_WAIT0()  asm volatile("cp.async.wait_group 0;" ::: "memory")
#define CP_WAIT1()  asm volatile("cp.async.wait_group 1;" ::: "memory")

#define MMA_F16(d, a, b) \
    asm volatile("mma.sync.aligned.m16n8k16.row.col.f32.f16.f16.f32 " \
                 "{%0,%1,%2,%3}, {%4,%5,%6,%7}, {%8,%9}, {%0,%1,%2,%3};" \
                 : "+f"(d[0]), "+f"(d[1]), "+f"(d[2]), "+f"(d[3]) \
                 : "r"(a[0]), "r"(a[1]), "r"(a[2]), "r"(a[3]), \
                   "r"(b[0]), "r"(b[1]))

__device__ __forceinline__ void ldsm_x4(uint32_t* r, uint32_t saddr) {
    asm volatile("ldmatrix.sync.aligned.m8n8.x4.shared.b16 {%0,%1,%2,%3}, [%4];"
                 : "=r"(r[0]), "=r"(r[1]), "=r"(r[2]), "=r"(r[3]) : "r"(saddr));
}
__device__ __forceinline__ uint32_t packh2(float a, float b) {
    __half2 h = __floats2half2_rn(a, b);
    return *(uint32_t*)&h;
}

// ===========================================================================
// fp16 mma.sync GEMM, ldmatrix fragments, 3-stage cp.async pipeline.
// C[M,N] = A[M,K](fp16) @ Bt[N,K](fp16)^T. Templated output type.
// ===========================================================================
#define BM 128
#define BN 128
#define BKH 64
#define PITCH 72
#define NSTG 3
#define STAGE_HALF (2 * 128 * PITCH)
#define STAGE_BYTES (STAGE_HALF * 2)
#define GEMM_SMEM (NSTG * STAGE_BYTES)    // 110592

template <typename OT>
__global__ __launch_bounds__(256, 2) void gemm_f16(
    const __half* __restrict__ A, const __half* __restrict__ Bt,
    OT* __restrict__ C, int M, int N, int K)
{
    extern __shared__ __half smh[];
    const int tid = threadIdx.x;
    const int warp = tid >> 5, lane = tid & 31;
    const int wm = (warp >> 2) * 64, wn = (warp & 3) * 32;
    const int m0 = blockIdx.y * BM, n0 = blockIdx.x * BN;
    const int NT = K / BKH;

    const int sel = lane >> 3, rr = lane & 7;
    const uint32_t sm0 = (uint32_t)__cvta_generic_to_shared(smh);
    const uint32_t aOff = ((uint32_t)(wm + (sel & 1) * 8 + rr) * PITCH + (sel >> 1) * 8) * 2;
    const uint32_t bOff = (uint32_t)(128 * PITCH) * 2 +
                          ((uint32_t)(wn + (sel >> 1) * 8 + rr) * PITCH + (sel & 1) * 8) * 2;

    float acc[4][4][4];
#pragma unroll
    for (int i = 0; i < 4; i++)
#pragma unroll
        for (int j = 0; j < 4; j++)
#pragma unroll
            for (int x = 0; x < 4; x++) acc[i][j][x] = 0.f;

    auto issue = [&](int kt) {
        __half* st = smh + (kt % NSTG) * STAGE_HALF;
        __half* As = st;
        __half* Bs = st + 128 * PITCH;
        const __half* Ag = A + (size_t)m0 * K + kt * BKH;
        const __half* Bg = Bt + (size_t)n0 * K + kt * BKH;
#pragma unroll
        for (int i = 0; i < 4; i++) {
            int idx = tid + i * 256;
            int r = idx >> 3, ch = idx & 7;
            cpasync16(As + r * PITCH + ch * 8, Ag + (size_t)r * K + ch * 8);
        }
#pragma unroll
        for (int i = 0; i < 4; i++) {
            int idx = tid + i * 256;
            int r = idx >> 3, ch = idx & 7;
            cpasync16(Bs + r * PITCH + ch * 8, Bg + (size_t)r * K + ch * 8);
        }
    };

    issue(0); CP_COMMIT();
    issue(1); CP_COMMIT();

    for (int kt = 0; kt < NT; kt++) {
        CP_WAIT1();               // stage kt resident
        __syncthreads();
        if (kt + 2 < NT) issue(kt + 2);
        CP_COMMIT();              // empty group at tail keeps wait-count exact

        const uint32_t stage = sm0 + (kt % NSTG) * STAGE_BYTES;
        const uint32_t aBase = stage + aOff;
        const uint32_t bBase = stage + bOff;
#pragma unroll
        for (int kc = 0; kc < 4; kc++) {
            uint32_t a[4][4], b2[2][4];
#pragma unroll
            for (int tm = 0; tm < 4; tm++)
                ldsm_x4(a[tm], aBase + (uint32_t)(tm * 16 * PITCH) * 2 + kc * 32);
#pragma unroll
            for (int tp = 0; tp < 2; tp++)
                ldsm_x4(b2[tp], bBase + (uint32_t)(tp * 16 * PITCH) * 2 + kc * 32);
#pragma unroll
            for (int tm = 0; tm < 4; tm++)
#pragma unroll
                for (int tn = 0; tn < 4; tn++)
                    MMA_F16(acc[tm][tn], a[tm], (&b2[tn >> 1][(tn & 1) * 2]));
        }
    }

    __syncthreads();
#pragma unroll
    for (int tm = 0; tm < 4; tm++) {
#pragma unroll
        for (int tn = 0; tn < 4; tn++) {
            int row = m0 + wm + tm * 16 + (lane >> 2);
            int col = n0 + wn + tn * 8 + 2 * (lane & 3);
            if constexpr (sizeof(OT) == 2) {
                *(__half2*)((__half*)C + (size_t)row * N + col) =
                    __floats2half2_rn(acc[tm][tn][0], acc[tm][tn][1]);
                *(__half2*)((__half*)C + (size_t)(row + 8) * N + col) =
                    __floats2half2_rn(acc[tm][tn][2], acc[tm][tn][3]);
            } else {
                *(float2*)((float*)C + (size_t)row * N + col) =
                    make_float2(acc[tm][tn][0], acc[tm][tn][1]);
                *(float2*)((float*)C + (size_t)(row + 8) * N + col) =
                    make_float2(acc[tm][tn][2], acc[tm][tn][3]);
            }
        }
    }
}

// ---------------------------------------------------------------------------
// Prep kernels
// ---------------------------------------------------------------------------
__global__ __launch_bounds__(256) void to_half(const float4* __restrict__ src,
                                               __half* __restrict__ dst, int n4)
{
    int i = blockIdx.x * 256 + threadIdx.x;
    if (i < n4) {
        float4 v = src[i];
        __half2* d = (__half2*)(dst + (size_t)i * 4);
        d[0] = __floats2half2_rn(v.x, v.y);
        d[1] = __floats2half2_rn(v.z, v.w);
    }
}

__global__ __launch_bounds__(256) void transpose_half(
    const float* __restrict__ src, __half* __restrict__ dst, int R, int C)
{
    __shared__ float t[32][33];
    const int bx = blockIdx.x * 32;
    const int by = blockIdx.y * 32;
    const int x = threadIdx.x & 31;
    const int y0 = (threadIdx.x >> 5) * 4;
#pragma unroll
    for (int j = 0; j < 4; j++)
        t[y0 + j][x] = src[(size_t)(by + y0 + j) * C + bx + x];
    __syncthreads();
#pragma unroll
    for (int j = 0; j < 4; j++)
        dst[(size_t)(bx + y0 + j) * R + by + x] = __float2half_rn(t[x][y0 + j]);
}

// V slice of fused QKV fp16 (row stride NQKV) -> Vt fp16 [b][kv][d][s]
__global__ __launch_bounds__(256) void transpose_vt(
    const __half* __restrict__ v, __half* __restrict__ vt)
{
    __shared__ __half t[32][34];
    const int bkv = blockIdx.z;
    const int b = bkv >> 2, kv = bkv & 3;
    const int s0 = blockIdx.y * 32;
    const int d0 = blockIdx.x * 32;
    const int x = threadIdx.x & 31;
    const int y0 = (threadIdx.x >> 5) * 4;
#pragma unroll
    for (int j = 0; j < 4; j++)
        t[y0 + j][x] = v[(size_t)(b * Sc + s0 + y0 + j) * NQKV + kv * HDc + d0 + x];
    __syncthreads();
#pragma unroll
    for (int j = 0; j < 4; j++)
        vt[(size_t)(bkv * HDc + d0 + y0 + j) * Sc + s0 + x] = t[x][y0 + j];
}

// ---------------------------------------------------------------------------
// RMSNorm + RoPE for BOTH Q and K in one launch.
// Blocks [0, M*Hc): Q slice (cols 0..4095), scale 1/16 -> g_qh.
// Blocks [M*Hc, M*Hc + M*KVc): K slice (cols 4096..5119), scale 1 -> g_kh.
// ---------------------------------------------------------------------------
__global__ __launch_bounds__(256) void rmsnorm_rope_qk(
    const __half* __restrict__ qkv, __half* __restrict__ qout,
    __half* __restrict__ kout, const float* __restrict__ qw,
    const float* __restrict__ kw, const int* __restrict__ pos_ids)
{
    const int M = Bc * Sc;
    int blk = blockIdx.x;
    const bool isQ = blk < M * Hc;
    int nh, colbase;
    const float* w;
    __half* outp;
    float oscale;
    if (isQ) { nh = Hc; colbase = 0; w = qw; outp = qout; oscale = 0.0625f; }
    else     { blk -= M * Hc; nh = KVc; colbase = Hc * HDc; w = kw; outp = kout; oscale = 1.0f; }

    const int d = threadIdx.x;
    const int head = blk % nh;
    const int bs = blk / nh;
    const int s = bs % Sc, b = bs / Sc;
    float v = __half2float(qkv[(size_t)bs * NQKV + colbase + head * HDc + d]);

    float sq = v * v;
#pragma unroll
    for (int o = 16; o; o >>= 1) sq += __shfl_xor_sync(0xffffffffu, sq, o);
    __shared__ float red[8];
    __shared__ float ys[256];
    if ((d & 31) == 0) red[d >> 5] = sq;
    __syncthreads();
    float tot = red[0] + red[1] + red[2] + red[3] + red[4] + red[5] + red[6] + red[7];
    float rstd = rsqrtf(tot * (1.0f / 256.0f) + 1e-6f);
    float y = v * rstd * (1.0f + w[d]);
    ys[d] = y;
    __syncthreads();
    float partner = (d < 128) ? -ys[d + 128] : ys[d - 128];

    float p = (float)pos_ids[s];
    float inv_freq = exp2f((float)(d & 127) * (-13.2877123795494f / 128.0f));
    float ang = p * inv_freq;
    float sv, cv;
    __sincosf(ang, &sv, &cv);
    outp[((size_t)(b * nh + head) * Sc + s) * HDc + d] =
        __float2half_rn((y * cv + partner * sv) * oscale);
}

// ===========================================================================
// FA2-style tensor-core flash attention (unchanged; passing at ~300 TF/s).
// ===========================================================================
#define FQP 264
#define FVP 72
#define F_KS (128 * FQP)
#define F_VS (F_KS + 2 * 64 * FQP)
#define FLASH_SMEM ((F_VS + 2 * 256 * FVP) * 2)

__global__ __launch_bounds__(256, 1) void flash_attn_tc(
    const __half* __restrict__ qh, const __half* __restrict__ kh,
    const __half* __restrict__ vt, __half* __restrict__ ob)
{
    extern __shared__ __half sm[];
    __half* Qs  = sm;
    __half* Ks0 = sm + F_KS;
    __half* Vs0 = sm + F_VS;

    const int qt = gridDim.x - 1 - blockIdx.x;
    const int q0 = qt * 128;
    const int h = blockIdx.y, b = blockIdx.z;
    const int kvh = h >> 2;
    const int tid = threadIdx.x;
    const int w = tid >> 5, lane = tid & 31;
    const int lr = lane >> 2, lc = lane & 3;
    const int sel = lane >> 3, rr = lane & 7;

    const __half* Qg = qh + ((size_t)(b * Hc + h) * Sc + q0) * HDc;
    const __half* Kg = kh + ((size_t)(b * KVc + kvh) * Sc) * HDc;
    const __half* Vg = vt + ((size_t)(b * KVc + kvh) * HDc) * Sc;

    auto issue_kv = [&](int t, int buf) {
        const int j0 = t * 64;
        __half* Kd = Ks0 + buf * 64 * FQP;
        __half* Vd = Vs0 + buf * 256 * FVP;
#pragma unroll
        for (int i = 0; i < 8; i++) {
            int idx = tid + i * 256;
            int r = idx >> 5, ch = idx & 31;
            cpasync16(Kd + r * FQP + ch * 8, Kg + (size_t)(j0 + r) * HDc + ch * 8);
        }
#pragma unroll
        for (int i = 0; i < 8; i++) {
            int idx = tid + i * 256;
            int r = idx >> 3, ch = idx & 7;
            cpasync16(Vd + r * FVP + ch * 8, Vg + (size_t)r * Sc + j0 + ch * 8);
        }
    };

#pragma unroll
    for (int i = 0; i < 16; i++) {
        int idx = tid + i * 256;
        int r = idx >> 5, ch = idx & 31;
        cpasync16(Qs + r * FQP + ch * 8, Qg + (size_t)r * HDc + ch * 8);
    }
    issue_kv(0, 0);
    CP_COMMIT();

    const uint32_t smb = (uint32_t)__cvta_generic_to_shared(sm);
    const uint32_t qA   = smb + ((uint32_t)(w * 16 + (sel & 1) * 8 + rr) * FQP + (sel >> 1) * 8) * 2;
    const uint32_t kOff = ((uint32_t)((sel >> 1) * 8 + rr) * FQP + (sel & 1) * 8) * 2;
    const uint32_t vOff = ((uint32_t)((sel >> 1) * 8 + rr) * FVP + (sel & 1) * 8) * 2;

    float oacc[32][4];
#pragma unroll
    for (int i = 0; i < 32; i++)
#pragma unroll
        for (int j = 0; j < 4; j++) oacc[i][j] = 0.f;
    float m0v = -1e30f, m1v = -1e30f, l0 = 0.f, l1 = 0.f;

    const int qg0 = q0 + w * 16 + lr;
    const int qg1 = qg0 + 8;
    const int qmaxw = q0 + w * 16 + 15;
    const int ntiles = q0 / 64 + 2;

    for (int t = 0; t < ntiles; t++) {
        CP_WAIT0();
        __syncthreads();
        if (t + 1 < ntiles) { issue_kv(t + 1, (t + 1) & 1); CP_COMMIT(); }
        const int j0 = t * 64;

        if (j0 <= qmaxw) {
            const uint32_t kB = smb + (uint32_t)(F_KS + (t & 1) * 64 * FQP) * 2 + kOff;
            const uint32_t vB = smb + (uint32_t)(F_VS + (t & 1) * 256 * FVP) * 2 + vOff;

            float sacc[8][4];
#pragma unroll
            for (int i = 0; i < 8; i++)
#pragma unroll
                for (int j = 0; j < 4; j++) sacc[i][j] = 0.f;
#pragma unroll
            for (int kc = 0; kc < 16; kc++) {
                uint32_t a[4];
                ldsm_x4(a, qA + kc * 32);
#pragma unroll
                for (int tp = 0; tp < 4; tp++) {
                    uint32_t bb[4];
                    ldsm_x4(bb, kB + (uint32_t)(tp * 16 * FQP) * 2 + kc * 32);
                    MMA_F16(sacc[2 * tp], a, (&bb[0]));
                    MMA_F16(sacc[2 * tp + 1], a, (&bb[2]));
                }
            }

            if (j0 + 63 > q0 + w * 16) {
#pragma unroll
                for (int nf = 0; nf < 8; nf++) {
                    int j = j0 + 8 * nf + 2 * lc;
                    if (j > qg0)     sacc[nf][0] = -1e30f;
                    if (j + 1 > qg0) sacc[nf][1] = -1e30f;
                    if (j > qg1)     sacc[nf][2] = -1e30f;
                    if (j + 1 > qg1) sacc[nf][3] = -1e30f;
                }
            }

            float mx0 = -1e30f, mx1 = -1e30f;
#pragma unroll
            for (int nf = 0; nf < 8; nf++) {
                mx0 = fmaxf(mx0, fmaxf(sacc[nf][0], sacc[nf][1]));
                mx1 = fmaxf(mx1, fmaxf(sacc[nf][2], sacc[nf][3]));
            }
            mx0 = fmaxf(mx0, __shfl_xor_sync(0xffffffffu, mx0, 1));
            mx0 = fmaxf(mx0, __shfl_xor_sync(0xffffffffu, mx0, 2));
            mx1 = fmaxf(mx1, __shfl_xor_sync(0xffffffffu, mx1, 1));
            mx1 = fmaxf(mx1, __shfl_xor_sync(0xffffffffu, mx1, 2));
            float mn0 = fmaxf(m0v, mx0), mn1 = fmaxf(m1v, mx1);
            float alpha0 = __expf(m0v - mn0);
            float alpha1 = __expf(m1v - mn1);
            m0v = mn0; m1v = mn1;

            float ps0 = 0.f, ps1 = 0.f;
#pragma unroll
            for (int nf = 0; nf < 8; nf++) {
                sacc[nf][0] = __expf(sacc[nf][0] - mn0);
                sacc[nf][1] = __expf(sacc[nf][1] - mn0);
                sacc[nf][2] = __expf(sacc[nf][2] - mn1);
                sacc[nf][3] = __expf(sacc[nf][3] - mn1);
                ps0 += sacc[nf][0] + sacc[nf][1];
                ps1 += sacc[nf][2] + sacc[nf][3];
            }
            ps0 += __shfl_xor_sync(0xffffffffu, ps0, 1);
            ps0 += __shfl_xor_sync(0xffffffffu, ps0, 2);
            ps1 += __shfl_xor_sync(0xffffffffu, ps1, 1);
            ps1 += __shfl_xor_sync(0xffffffffu, ps1, 2);
            l0 = l0 * alpha0 + ps0;
            l1 = l1 * alpha1 + ps1;

#pragma unroll
            for (int nf = 0; nf < 32; nf++) {
                oacc[nf][0] *= alpha0; oacc[nf][1] *= alpha0;
                oacc[nf][2] *= alpha1; oacc[nf][3] *= alpha1;
            }

#pragma unroll
            for (int kc = 0; kc < 4; kc++) {
                uint32_t pa[4];
                pa[0] = packh2(sacc[2 * kc][0],     sacc[2 * kc][1]);
                pa[1] = packh2(sacc[2 * kc][2],     sacc[2 * kc][3]);
                pa[2] = packh2(sacc[2 * kc + 1][0], sacc[2 * kc + 1][1]);
                pa[3] = packh2(sacc[2 * kc + 1][2], sacc[2 * kc + 1][3]);
#pragma unroll
                for (int tp = 0; tp < 16; tp++) {
                    uint32_t bb[4];
                    ldsm_x4(bb, vB + (uint32_t)(tp * 16 * FVP) * 2 + kc * 32);
                    MMA_F16(oacc[2 * tp], pa, (&bb[0]));
                    MMA_F16(oacc[2 * tp + 1], pa, (&bb[2]));
                }
            }
        }
    }

    const float inv0 = 1.f / l0;
    const float inv1 = 1.f / l1;
#pragma unroll
    for (int nf = 0; nf < 32; nf++) {
        int col = h * HDc + 8 * nf + 2 * lc;
        size_t r0a = (size_t)(b * Sc + q0 + w * 16 + lr) * (Hc * HDc) + col;
        size_t r1a = (size_t)(b * Sc + q0 + w * 16 + lr + 8) * (Hc * HDc) + col;
        *(__half2*)(ob + r0a) = __floats2half2_rn(oacc[nf][0] * inv0, oacc[nf][1] * inv0);
        *(__half2*)(ob + r1a) = __floats2half2_rn(oacc[nf][2] * inv1, oacc[nf][3] * inv1);
    }
}

// ---------------------------------------------------------------------------
extern "C" void kernel_launch(void* const* d_in, const int* in_sizes, int n_in,
                              void* d_out, int out_size)
{
    const float* hidden = (const float*)d_in[0];
    const float* Wq = (const float*)d_in[1];
    const float* Wk = (const float*)d_in[2];
    const float* Wv = (const float*)d_in[3];
    const float* Wo = (const float*)d_in[4];
    const float* qw = (const float*)d_in[5];
    const float* kw = (const float*)d_in[6];
    const int*  pos = (const int*)d_in[7];
    float* out = (float*)d_out;

    __half *qkvh, *qhh, *khh, *vth, *ah, *hh, *wqkvT, *woT;
    cudaGetSymbolAddress((void**)&qkvh, g_qkvh);
    cudaGetSymbolAddress((void**)&qhh, g_qh);
    cudaGetSymbolAddress((void**)&khh, g_kh);
    cudaGetSymbolAddress((void**)&vth, g_vt);
    cudaGetSymbolAddress((void**)&ah, g_attn_h);
    cudaGetSymbolAddress((void**)&hh, g_hh);
    cudaGetSymbolAddress((void**)&wqkvT, g_wqkvT);
    cudaGetSymbolAddress((void**)&woT, g_woT);

    const int M = Bc * Sc;           // 4096
    const int NQ = Hc * HDc;         // 4096
    const int NKV = KVc * HDc;       // 1024

    cudaFuncSetAttribute(gemm_f16<__half>, cudaFuncAttributeMaxDynamicSharedMemorySize, GEMM_SMEM);
    cudaFuncSetAttribute(gemm_f16<float>, cudaFuncAttributeMaxDynamicSharedMemorySize, GEMM_SMEM);
    cudaFuncSetAttribute(flash_attn_tc, cudaFuncAttributeMaxDynamicSharedMemorySize, FLASH_SMEM);

    // Prep: hidden -> fp16; weights -> fused transposed fp16 + Wo
    {
        int n4 = M * Dc / 4;
        to_half<<<(n4 + 255) / 256, 256>>>((const float4*)hidden, hh, n4);
    }
    transpose_half<<<dim3(NQ / 32, Dc / 32), 256>>>(Wq, wqkvT, Dc, NQ);
    transpose_half<<<dim3(NKV / 32, Dc / 32), 256>>>(Wk, wqkvT + (size_t)NQ * Dc, Dc, NKV);
    transpose_half<<<dim3(NKV / 32, Dc / 32), 256>>>(Wv, wqkvT + (size_t)(NQ + NKV) * Dc, Dc, NKV);
    transpose_half<<<dim3(Dc / 32, NQ / 32), 256>>>(Wo, woT, NQ, Dc);

    // Fused QKV projection -> fp16
    gemm_f16<__half><<<dim3(NQKV / BN, M / BM), 256, GEMM_SMEM>>>(hh, wqkvT, qkvh, M, NQKV, Dc);

    // RMSNorm + RoPE for Q and K in one launch; V -> transposed
    rmsnorm_rope_qk<<<M * (Hc + KVc), 256>>>(qkvh, qhh, khh, qw, kw, pos);
    transpose_vt<<<dim3(HDc / 32, Sc / 32, Bc * KVc), 256>>>(qkvh + NQ + NKV, vth);

    // FA2-style tensor-core flash attention
    flash_attn_tc<<<dim3(Sc / 128, Hc, Bc), 256, FLASH_SMEM>>>(qhh, khh, vth, ah);

    // Output projection -> fp32
    gemm_f16<float><<<dim3(Dc / BN, M / BM), 256, GEMM_SMEM>>>(ah, woT, out, M, Dc, NQ);
}

// round 10
// speedup vs baseline: 7.8564x; 1.0112x over previous
#include <cuda_runtime.h>
#include <cuda_fp16.h>
#include <cstdint>

// Problem constants (Gemma4 attention): B=2, S=2048, D=2048, H=16, KV=4, HD=256
#define Bc 2
#define Sc 2048
#define Dc 2048
#define Hc 16
#define KVc 4
#define HDc 256
#define NQKV 6144   // H*HD + 2*KV*HD

// Scratch (__device__ globals; no cudaMalloc allowed)
__device__ __half g_qkvh[(size_t)Bc * Sc * NQKV];        // fused QKV out fp16
__device__ __half g_qh[(size_t)Bc * Hc * Sc * HDc];      // [b][h][s][d] (scaled 1/16*log2e)
__device__ __half g_kh[(size_t)Bc * KVc * Sc * HDc];     // [b][kv][s][d]
__device__ __half g_vt[(size_t)Bc * KVc * HDc * Sc];     // [b][kv][d][s]
__device__ __half g_attn_h[(size_t)Bc * Sc * Hc * HDc];  // [b,s][h*HD] fp16
__device__ __half g_hh[(size_t)Bc * Sc * Dc];            // hidden fp16
__device__ __half g_wqkvT[(size_t)NQKV * Dc];            // [6144][2048] fp16
__device__ __half g_woT[(size_t)Dc * (Hc * HDc)];        // [2048][4096]

// ===========================================================================
// Common PTX helpers
// ===========================================================================
__device__ __forceinline__ void cpasync16(const void* smem_dst, const void* gsrc) {
    uint32_t d = (uint32_t)__cvta_generic_to_shared(smem_dst);
    asm volatile("cp.async.cg.shared.global [%0], [%1], 16;" :: "r"(d), "l"(gsrc));
}
#define CP_COMMIT() asm volatile("cp.async.commit_group;" ::: "memory")
#define CP_WAIT0()  asm volatile("cp.async.wait_group 0;" ::: "memory")
#define CP_WAIT1()  asm volatile("cp.async.wait_group 1;" ::: "memory")

#define MMA_F16(d, a, b) \
    asm volatile("mma.sync.aligned.m16n8k16.row.col.f32.f16.f16.f32 " \
                 "{%0,%1,%2,%3}, {%4,%5,%6,%7}, {%8,%9}, {%0,%1,%2,%3};" \
                 : "+f"(d[0]), "+f"(d[1]), "+f"(d[2]), "+f"(d[3]) \
                 : "r"(a[0]), "r"(a[1]), "r"(a[2]), "r"(a[3]), \
                   "r"(b[0]), "r"(b[1]))

__device__ __forceinline__ void ldsm_x4(uint32_t* r, uint32_t saddr) {
    asm volatile("ldmatrix.sync.aligned.m8n8.x4.shared.b16 {%0,%1,%2,%3}, [%4];"
                 : "=r"(r[0]), "=r"(r[1]), "=r"(r[2]), "=r"(r[3]) : "r"(saddr));
}
__device__ __forceinline__ uint32_t packh2(float a, float b) {
    __half2 h = __floats2half2_rn(a, b);
    return *(uint32_t*)&h;
}
__device__ __forceinline__ float ex2(float x) {
    float r;
    asm("ex2.approx.ftz.f32 %0, %1;" : "=f"(r) : "f"(x));
    return r;
}

// ===========================================================================
// fp16 mma.sync GEMM, ldmatrix fragments, 3-stage cp.async pipeline.
// C[M,N] = A[M,K](fp16) @ Bt[N,K](fp16)^T. Templated output type.
// ===========================================================================
#define BM 128
#define BN 128
#define BKH 64
#define PITCH 72
#define NSTG 3
#define STAGE_HALF (2 * 128 * PITCH)
#define STAGE_BYTES (STAGE_HALF * 2)
#define GEMM_SMEM (NSTG * STAGE_BYTES)    // 110592

template <typename OT>
__global__ __launch_bounds__(256, 2) void gemm_f16(
    const __half* __restrict__ A, const __half* __restrict__ Bt,
    OT* __restrict__ C, int M, int N, int K)
{
    extern __shared__ __half smh[];
    const int tid = threadIdx.x;
    const int warp = tid >> 5, lane = tid & 31;
    const int wm = (warp >> 2) * 64, wn = (warp & 3) * 32;
    const int m0 = blockIdx.y * BM, n0 = blockIdx.x * BN;
    const int NT = K / BKH;

    const int sel = lane >> 3, rr = lane & 7;
    const uint32_t sm0 = (uint32_t)__cvta_generic_to_shared(smh);
    const uint32_t aOff = ((uint32_t)(wm + (sel & 1) * 8 + rr) * PITCH + (sel >> 1) * 8) * 2;
    const uint32_t bOff = (uint32_t)(128 * PITCH) * 2 +
                          ((uint32_t)(wn + (sel >> 1) * 8 + rr) * PITCH + (sel & 1) * 8) * 2;

    float acc[4][4][4];
#pragma unroll
    for (int i = 0; i < 4; i++)
#pragma unroll
        for (int j = 0; j < 4; j++)
#pragma unroll
            for (int x = 0; x < 4; x++) acc[i][j][x] = 0.f;

    auto issue = [&](int kt) {
        __half* st = smh + (kt % NSTG) * STAGE_HALF;
        __half* As = st;
        __half* Bs = st + 128 * PITCH;
        const __half* Ag = A + (size_t)m0 * K + kt * BKH;
        const __half* Bg = Bt + (size_t)n0 * K + kt * BKH;
#pragma unroll
        for (int i = 0; i < 4; i++) {
            int idx = tid + i * 256;
            int r = idx >> 3, ch = idx & 7;
            cpasync16(As + r * PITCH + ch * 8, Ag + (size_t)r * K + ch * 8);
        }
#pragma unroll
        for (int i = 0; i < 4; i++) {
            int idx = tid + i * 256;
            int r = idx >> 3, ch = idx & 7;
            cpasync16(Bs + r * PITCH + ch * 8, Bg + (size_t)r * K + ch * 8);
        }
    };

    issue(0); CP_COMMIT();
    issue(1); CP_COMMIT();

    for (int kt = 0; kt < NT; kt++) {
        CP_WAIT1();
        __syncthreads();
        if (kt + 2 < NT) issue(kt + 2);
        CP_COMMIT();

        const uint32_t stage = sm0 + (kt % NSTG) * STAGE_BYTES;
        const uint32_t aBase = stage + aOff;
        const uint32_t bBase = stage + bOff;
#pragma unroll
        for (int kc = 0; kc < 4; kc++) {
            uint32_t a[4][4], b2[2][4];
#pragma unroll
            for (int tm = 0; tm < 4; tm++)
                ldsm_x4(a[tm], aBase + (uint32_t)(tm * 16 * PITCH) * 2 + kc * 32);
#pragma unroll
            for (int tp = 0; tp < 2; tp++)
                ldsm_x4(b2[tp], bBase + (uint32_t)(tp * 16 * PITCH) * 2 + kc * 32);
#pragma unroll
            for (int tm = 0; tm < 4; tm++)
#pragma unroll
                for (int tn = 0; tn < 4; tn++)
                    MMA_F16(acc[tm][tn], a[tm], (&b2[tn >> 1][(tn & 1) * 2]));
        }
    }

    __syncthreads();
#pragma unroll
    for (int tm = 0; tm < 4; tm++) {
#pragma unroll
        for (int tn = 0; tn < 4; tn++) {
            int row = m0 + wm + tm * 16 + (lane >> 2);
            int col = n0 + wn + tn * 8 + 2 * (lane & 3);
            if constexpr (sizeof(OT) == 2) {
                *(__half2*)((__half*)C + (size_t)row * N + col) =
                    __floats2half2_rn(acc[tm][tn][0], acc[tm][tn][1]);
                *(__half2*)((__half*)C + (size_t)(row + 8) * N + col) =
                    __floats2half2_rn(acc[tm][tn][2], acc[tm][tn][3]);
            } else {
                *(float2*)((float*)C + (size_t)row * N + col) =
                    make_float2(acc[tm][tn][0], acc[tm][tn][1]);
                *(float2*)((float*)C + (size_t)(row + 8) * N + col) =
                    make_float2(acc[tm][tn][2], acc[tm][tn][3]);
            }
        }
    }
}

// ---------------------------------------------------------------------------
// Prep kernels
// ---------------------------------------------------------------------------
__global__ __launch_bounds__(256) void to_half(const float4* __restrict__ src,
                                               __half* __restrict__ dst, int n4)
{
    int i = blockIdx.x * 256 + threadIdx.x;
    if (i < n4) {
        float4 v = src[i];
        __half2* d = (__half2*)(dst + (size_t)i * 4);
        d[0] = __floats2half2_rn(v.x, v.y);
        d[1] = __floats2half2_rn(v.z, v.w);
    }
}

__global__ __launch_bounds__(256) void transpose_half(
    const float* __restrict__ src, __half* __restrict__ dst, int R, int C)
{
    __shared__ float t[32][33];
    const int bx = blockIdx.x * 32;
    const int by = blockIdx.y * 32;
    const int x = threadIdx.x & 31;
    const int y0 = (threadIdx.x >> 5) * 4;
#pragma unroll
    for (int j = 0; j < 4; j++)
        t[y0 + j][x] = src[(size_t)(by + y0 + j) * C + bx + x];
    __syncthreads();
#pragma unroll
    for (int j = 0; j < 4; j++)
        dst[(size_t)(bx + y0 + j) * R + by + x] = __float2half_rn(t[x][y0 + j]);
}

// V slice of fused QKV fp16 (row stride NQKV) -> Vt fp16 [b][kv][d][s]
__global__ __launch_bounds__(256) void transpose_vt(
    const __half* __restrict__ v, __half* __restrict__ vt)
{
    __shared__ __half t[32][34];
    const int bkv = blockIdx.z;
    const int b = bkv >> 2, kv = bkv & 3;
    const int s0 = blockIdx.y * 32;
    const int d0 = blockIdx.x * 32;
    const int x = threadIdx.x & 31;
    const int y0 = (threadIdx.x >> 5) * 4;
#pragma unroll
    for (int j = 0; j < 4; j++)
        t[y0 + j][x] = v[(size_t)(b * Sc + s0 + y0 + j) * NQKV + kv * HDc + d0 + x];
    __syncthreads();
#pragma unroll
    for (int j = 0; j < 4; j++)
        vt[(size_t)(bkv * HDc + d0 + y0 + j) * Sc + s0 + x] = t[x][y0 + j];
}

// ---------------------------------------------------------------------------
// RMSNorm + RoPE for BOTH Q and K in one launch.
// Q gets oscale = (1/16)*log2(e) -> softmax runs in base-2 domain.
// ---------------------------------------------------------------------------
__global__ __launch_bounds__(256) void rmsnorm_rope_qk(
    const __half* __restrict__ qkv, __half* __restrict__ qout,
    __half* __restrict__ kout, const float* __restrict__ qw,
    const float* __restrict__ kw, const int* __restrict__ pos_ids)
{
    const int M = Bc * Sc;
    int blk = blockIdx.x;
    const bool isQ = blk < M * Hc;
    int nh, colbase;
    const float* w;
    __half* outp;
    float oscale;
    if (isQ) { nh = Hc; colbase = 0; w = qw; outp = qout;
               oscale = 0.0625f * 1.44269504088896f; }
    else     { blk -= M * Hc; nh = KVc; colbase = Hc * HDc; w = kw; outp = kout; oscale = 1.0f; }

    const int d = threadIdx.x;
    const int head = blk % nh;
    const int bs = blk / nh;
    const int s = bs % Sc, b = bs / Sc;
    float v = __half2float(qkv[(size_t)bs * NQKV + colbase + head * HDc + d]);

    float sq = v * v;
#pragma unroll
    for (int o = 16; o; o >>= 1) sq += __shfl_xor_sync(0xffffffffu, sq, o);
    __shared__ float red[8];
    __shared__ float ys[256];
    if ((d & 31) == 0) red[d >> 5] = sq;
    __syncthreads();
    float tot = red[0] + red[1] + red[2] + red[3] + red[4] + red[5] + red[6] + red[7];
    float rstd = rsqrtf(tot * (1.0f / 256.0f) + 1e-6f);
    float y = v * rstd * (1.0f + w[d]);
    ys[d] = y;
    __syncthreads();
    float partner = (d < 128) ? -ys[d + 128] : ys[d - 128];

    float p = (float)pos_ids[s];
    float inv_freq = exp2f((float)(d & 127) * (-13.2877123795494f / 128.0f));
    float ang = p * inv_freq;
    float sv, cv;
    __sincosf(ang, &sv, &cv);
    outp[((size_t)(b * nh + head) * Sc + s) * HDc + d] =
        __float2half_rn((y * cv + partner * sv) * oscale);
}

// ===========================================================================
// FA2-style tensor-core flash attention. Softmax in base-2 (Q pre-scaled).
// ===========================================================================
#define FQP 264
#define FVP 72
#define F_KS (128 * FQP)
#define F_VS (F_KS + 2 * 64 * FQP)
#define FLASH_SMEM ((F_VS + 2 * 256 * FVP) * 2)

__global__ __launch_bounds__(256, 1) void flash_attn_tc(
    const __half* __restrict__ qh, const __half* __restrict__ kh,
    const __half* __restrict__ vt, __half* __restrict__ ob)
{
    extern __shared__ __half sm[];
    __half* Qs  = sm;
    __half* Ks0 = sm + F_KS;
    __half* Vs0 = sm + F_VS;

    const int qt = gridDim.x - 1 - blockIdx.x;
    const int q0 = qt * 128;
    const int h = blockIdx.y, b = blockIdx.z;
    const int kvh = h >> 2;
    const int tid = threadIdx.x;
    const int w = tid >> 5, lane = tid & 31;
    const int lr = lane >> 2, lc = lane & 3;
    const int sel = lane >> 3, rr = lane & 7;

    const __half* Qg = qh + ((size_t)(b * Hc + h) * Sc + q0) * HDc;
    const __half* Kg = kh + ((size_t)(b * KVc + kvh) * Sc) * HDc;
    const __half* Vg = vt + ((size_t)(b * KVc + kvh) * HDc) * Sc;

    auto issue_kv = [&](int t, int buf) {
        const int j0 = t * 64;
        __half* Kd = Ks0 + buf * 64 * FQP;
        __half* Vd = Vs0 + buf * 256 * FVP;
#pragma unroll
        for (int i = 0; i < 8; i++) {
            int idx = tid + i * 256;
            int r = idx >> 5, ch = idx & 31;
            cpasync16(Kd + r * FQP + ch * 8, Kg + (size_t)(j0 + r) * HDc + ch * 8);
        }
#pragma unroll
        for (int i = 0; i < 8; i++) {
            int idx = tid + i * 256;
            int r = idx >> 3, ch = idx & 7;
            cpasync16(Vd + r * FVP + ch * 8, Vg + (size_t)r * Sc + j0 + ch * 8);
        }
    };

#pragma unroll
    for (int i = 0; i < 16; i++) {
        int idx = tid + i * 256;
        int r = idx >> 5, ch = idx & 31;
        cpasync16(Qs + r * FQP + ch * 8, Qg + (size_t)r * HDc + ch * 8);
    }
    issue_kv(0, 0);
    CP_COMMIT();

    const uint32_t smb = (uint32_t)__cvta_generic_to_shared(sm);
    const uint32_t qA   = smb + ((uint32_t)(w * 16 + (sel & 1) * 8 + rr) * FQP + (sel >> 1) * 8) * 2;
    const uint32_t kOff = ((uint32_t)((sel >> 1) * 8 + rr) * FQP + (sel & 1) * 8) * 2;
    const uint32_t vOff = ((uint32_t)((sel >> 1) * 8 + rr) * FVP + (sel & 1) * 8) * 2;

    float oacc[32][4];
#pragma unroll
    for (int i = 0; i < 32; i++)
#pragma unroll
        for (int j = 0; j < 4; j++) oacc[i][j] = 0.f;
    float m0v = -1e30f, m1v = -1e30f, l0 = 0.f, l1 = 0.f;

    const int qg0 = q0 + w * 16 + lr;
    const int qg1 = qg0 + 8;
    const int qmaxw = q0 + w * 16 + 15;
    const int ntiles = q0 / 64 + 2;

    for (int t = 0; t < ntiles; t++) {
        CP_WAIT0();
        __syncthreads();
        if (t + 1 < ntiles) { issue_kv(t + 1, (t + 1) & 1); CP_COMMIT(); }
        const int j0 = t * 64;

        if (j0 <= qmaxw) {
            const uint32_t kB = smb + (uint32_t)(F_KS + (t & 1) * 64 * FQP) * 2 + kOff;
            const uint32_t vB = smb + (uint32_t)(F_VS + (t & 1) * 256 * FVP) * 2 + vOff;

            float sacc[8][4];
#pragma unroll
            for (int i = 0; i < 8; i++)
#pragma unroll
                for (int j = 0; j < 4; j++) sacc[i][j] = 0.f;
#pragma unroll
            for (int kc = 0; kc < 16; kc++) {
                uint32_t a[4];
                ldsm_x4(a, qA + kc * 32);
#pragma unroll
                for (int tp = 0; tp < 4; tp++) {
                    uint32_t bb[4];
                    ldsm_x4(bb, kB + (uint32_t)(tp * 16 * FQP) * 2 + kc * 32);
                    MMA_F16(sacc[2 * tp], a, (&bb[0]));
                    MMA_F16(sacc[2 * tp + 1], a, (&bb[2]));
                }
            }

            if (j0 + 63 > q0 + w * 16) {
#pragma unroll
                for (int nf = 0; nf < 8; nf++) {
                    int j = j0 + 8 * nf + 2 * lc;
                    if (j > qg0)     sacc[nf][0] = -1e30f;
                    if (j + 1 > qg0) sacc[nf][1] = -1e30f;
                    if (j > qg1)     sacc[nf][2] = -1e30f;
                    if (j + 1 > qg1) sacc[nf][3] = -1e30f;
                }
            }

            float mx0 = -1e30f, mx1 = -1e30f;
#pragma unroll
            for (int nf = 0; nf < 8; nf++) {
                mx0 = fmaxf(mx0, fmaxf(sacc[nf][0], sacc[nf][1]));
                mx1 = fmaxf(mx1, fmaxf(sacc[nf][2], sacc[nf][3]));
            }
            mx0 = fmaxf(mx0, __shfl_xor_sync(0xffffffffu, mx0, 1));
            mx0 = fmaxf(mx0, __shfl_xor_sync(0xffffffffu, mx0, 2));
            mx1 = fmaxf(mx1, __shfl_xor_sync(0xffffffffu, mx1, 1));
            mx1 = fmaxf(mx1, __shfl_xor_sync(0xffffffffu, mx1, 2));
            float mn0 = fmaxf(m0v, mx0), mn1 = fmaxf(m1v, mx1);
            float alpha0 = ex2(m0v - mn0);
            float alpha1 = ex2(m1v - mn1);
            m0v = mn0; m1v = mn1;

            float ps0 = 0.f, ps1 = 0.f;
#pragma unroll
            for (int nf = 0; nf < 8; nf++) {
                sacc[nf][0] = ex2(sacc[nf][0] - mn0);
                sacc[nf][1] = ex2(sacc[nf][1] - mn0);
                sacc[nf][2] = ex2(sacc[nf][2] - mn1);
                sacc[nf][3] = ex2(sacc[nf][3] - mn1);
                ps0 += sacc[nf][0] + sacc[nf][1];
                ps1 += sacc[nf][2] + sacc[nf][3];
            }
            ps0 += __shfl_xor_sync(0xffffffffu, ps0, 1);
            ps0 += __shfl_xor_sync(0xffffffffu, ps0, 2);
            ps1 += __shfl_xor_sync(0xffffffffu, ps1, 1);
            ps1 += __shfl_xor_sync(0xffffffffu, ps1, 2);
            l0 = l0 * alpha0 + ps0;
            l1 = l1 * alpha1 + ps1;

#pragma unroll
            for (int nf = 0; nf < 32; nf++) {
                oacc[nf][0] *= alpha0; oacc[nf][1] *= alpha0;
                oacc[nf][2] *= alpha1; oacc[nf][3] *= alpha1;
            }

#pragma unroll
            for (int kc = 0; kc < 4; kc++) {
                uint32_t pa[4];
                pa[0] = packh2(sacc[2 * kc][0],     sacc[2 * kc][1]);
                pa[1] = packh2(sacc[2 * kc][2],     sacc[2 * kc][3]);
                pa[2] = packh2(sacc[2 * kc + 1][0], sacc[2 * kc + 1][1]);
                pa[3] = packh2(sacc[2 * kc + 1][2], sacc[2 * kc + 1][3]);
#pragma unroll
                for (int tp = 0; tp < 16; tp++) {
                    uint32_t bb[4];
                    ldsm_x4(bb, vB + (uint32_t)(tp * 16 * FVP) * 2 + kc * 32);
                    MMA_F16(oacc[2 * tp], pa, (&bb[0]));
                    MMA_F16(oacc[2 * tp + 1], pa, (&bb[2]));
                }
            }
        }
    }

    const float inv0 = 1.f / l0;
    const float inv1 = 1.f / l1;
#pragma unroll
    for (int nf = 0; nf < 32; nf++) {
        int col = h * HDc + 8 * nf + 2 * lc;
        size_t r0a = (size_t)(b * Sc + q0 + w * 16 + lr) * (Hc * HDc) + col;
        size_t r1a = (size_t)(b * Sc + q0 + w * 16 + lr + 8) * (Hc * HDc) + col;
        *(__half2*)(ob + r0a) = __floats2half2_rn(oacc[nf][0] * inv0, oacc[nf][1] * inv0);
        *(__half2*)(ob + r1a) = __floats2half2_rn(oacc[nf][2] * inv1, oacc[nf][3] * inv1);
    }
}

// ---------------------------------------------------------------------------
extern "C" void kernel_launch(void* const* d_in, const int* in_sizes, int n_in,
                              void* d_out, int out_size)
{
    const float* hidden = (const float*)d_in[0];
    const float* Wq = (const float*)d_in[1];
    const float* Wk = (const float*)d_in[2];
    const float* Wv = (const float*)d_in[3];
    const float* Wo = (const float*)d_in[4];
    const float* qw = (const float*)d_in[5];
    const float* kw = (const float*)d_in[6];
    const int*  pos = (const int*)d_in[7];
    float* out = (float*)d_out;

    __half *qkvh, *qhh, *khh, *vth, *ah, *hh, *wqkvT, *woT;
    cudaGetSymbolAddress((void**)&qkvh, g_qkvh);
    cudaGetSymbolAddress((void**)&qhh, g_qh);
    cudaGetSymbolAddress((void**)&khh, g_kh);
    cudaGetSymbolAddress((void**)&vth, g_vt);
    cudaGetSymbolAddress((void**)&ah, g_attn_h);
    cudaGetSymbolAddress((void**)&hh, g_hh);
    cudaGetSymbolAddress((void**)&wqkvT, g_wqkvT);
    cudaGetSymbolAddress((void**)&woT, g_woT);

    const int M = Bc * Sc;           // 4096
    const int NQ = Hc * HDc;         // 4096
    const int NKV = KVc * HDc;       // 1024

    cudaFuncSetAttribute(gemm_f16<__half>, cudaFuncAttributeMaxDynamicSharedMemorySize, GEMM_SMEM);
    cudaFuncSetAttribute(gemm_f16<float>, cudaFuncAttributeMaxDynamicSharedMemorySize, GEMM_SMEM);
    cudaFuncSetAttribute(flash_attn_tc, cudaFuncAttributeMaxDynamicSharedMemorySize, FLASH_SMEM);

    // Side streams + events for capturable fork/join (created+destroyed per call;
    // host-side only, no device allocations).
    cudaStream_t s1, s2;
    cudaStreamCreateWithFlags(&s1, cudaStreamNonBlocking);
    cudaStreamCreateWithFlags(&s2, cudaStreamNonBlocking);
    cudaEvent_t evRoot, evKV, evQ, evWo, evG, evVt;
    cudaEventCreateWithFlags(&evRoot, cudaEventDisableTiming);
    cudaEventCreateWithFlags(&evKV, cudaEventDisableTiming);
    cudaEventCreateWithFlags(&evQ, cudaEventDisableTiming);
    cudaEventCreateWithFlags(&evWo, cudaEventDisableTiming);
    cudaEventCreateWithFlags(&evG, cudaEventDisableTiming);
    cudaEventCreateWithFlags(&evVt, cudaEventDisableTiming);

    // Fork s1/s2 off the main (capture) stream
    cudaEventRecord(evRoot, 0);
    cudaStreamWaitEvent(s1, evRoot, 0);
    cudaStreamWaitEvent(s2, evRoot, 0);

    // main: hidden -> fp16
    {
        int n4 = M * Dc / 4;
        to_half<<<(n4 + 255) / 256, 256>>>((const float4*)hidden, hh, n4);
    }
    // s1: Wk, Wv (needed by QKV gemm), then Wo (needed only by final gemm)
    transpose_half<<<dim3(NKV / 32, Dc / 32), 256, 0, s1>>>(Wk, wqkvT + (size_t)NQ * Dc, Dc, NKV);
    transpose_half<<<dim3(NKV / 32, Dc / 32), 256, 0, s1>>>(Wv, wqkvT + (size_t)(NQ + NKV) * Dc, Dc, NKV);
    cudaEventRecord(evKV, s1);
    transpose_half<<<dim3(Dc / 32, NQ / 32), 256, 0, s1>>>(Wo, woT, NQ, Dc);
    cudaEventRecord(evWo, s1);
    // s2: Wq
    transpose_half<<<dim3(NQ / 32, Dc / 32), 256, 0, s2>>>(Wq, wqkvT, Dc, NQ);
    cudaEventRecord(evQ, s2);

    // join weight deps -> fused QKV projection on main stream
    cudaStreamWaitEvent(0, evKV, 0);
    cudaStreamWaitEvent(0, evQ, 0);
    gemm_f16<__half><<<dim3(NQKV / BN, M / BM), 256, GEMM_SMEM>>>(hh, wqkvT, qkvh, M, NQKV, Dc);

    // fork: transpose_vt (s1, after Wo) parallel with rmsnorm (main)
    cudaEventRecord(evG, 0);
    cudaStreamWaitEvent(s1, evG, 0);
    transpose_vt<<<dim3(HDc / 32, Sc / 32, Bc * KVc), 256, 0, s1>>>(qkvh + NQ + NKV, vth);
    cudaEventRecord(evVt, s1);
    rmsnorm_rope_qk<<<M * (Hc + KVc), 256>>>(qkvh, qhh, khh, qw, kw, pos);

    // join: flash needs rmsnorm (main) + vt (s1)
    cudaStreamWaitEvent(0, evVt, 0);
    flash_attn_tc<<<dim3(Sc / 128, Hc, Bc), 256, FLASH_SMEM>>>(qhh, khh, vth, ah);

    // join Wo, then output projection
    cudaStreamWaitEvent(0, evWo, 0);
    gemm_f16<float><<<dim3(Dc / BN, M / BM), 256, GEMM_SMEM>>>(ah, woT, out, M, Dc, NQ);

    cudaEventDestroy(evRoot);
    cudaEventDestroy(evKV);
    cudaEventDestroy(evQ);
    cudaEventDestroy(evWo);
    cudaEventDestroy(evG);
    cudaEventDestroy(evVt);
    cudaStreamDestroy(s1);
    cudaStreamDestroy(s2);
}